// round 5
// baseline (speedup 1.0000x reference)
#include <cuda_runtime.h>
#include <math.h>

#define SEQ   2048
#define HID   2048
#define HDIM  128
#define NHEAD 16
#define KVDIM 512
#define FFD   4096
#define NEXP  8
#define NASSIGN (2*SEQ)

#define BM  128
#define BN  128
#define BKK 16

// ---------------- scratch (device globals: allocation-free rule) ----------------
__device__ float g_x[SEQ*HID];        // rmsnorm1 out
__device__ float g_q[SEQ*HID];
__device__ float g_k[SEQ*KVDIM];
__device__ float g_v[SEQ*KVDIM];
__device__ float g_attn[SEQ*HID];     // attention output (pre O-proj)
__device__ float g_h[SEQ*HID];        // residual after attention
__device__ float g_x2[SEQ*HID];       // rmsnorm2 out
__device__ int   g_topi[SEQ*2];
__device__ float g_topv[SEQ*2];
__device__ int   g_tok[NASSIGN];
__device__ float g_wgt[NASSIGN];
__device__ int   g_cnt[NEXP];
__device__ int   g_off[NEXP];
__device__ float g_t1[NASSIGN*FFD];   // 64 MB: gate-proj then swiglu result
__device__ float g_t3[NASSIGN*FFD];   // 64 MB: up-proj

// ---------------- rmsnorm ----------------
__global__ void rmsnorm_kernel(const float* __restrict__ hidden,
                               const float* __restrict__ w, int mode)
{
    const float* in  = mode ? g_h  : hidden;
    float*       out = mode ? g_x2 : g_x;
    int row = blockIdx.x;
    const float* x = in + (size_t)row*HID;
    __shared__ float red[256];
    float ss = 0.f;
    for (int i = threadIdx.x; i < HID; i += 256) { float v = x[i]; ss += v*v; }
    red[threadIdx.x] = ss; __syncthreads();
    for (int s = 128; s > 0; s >>= 1) {
        if (threadIdx.x < s) red[threadIdx.x] += red[threadIdx.x+s];
        __syncthreads();
    }
    float rs = rsqrtf(red[0]/(float)HID + 1e-5f);
    float* o = out + (size_t)row*HID;
    for (int i = threadIdx.x; i < HID; i += 256) o[i] = x[i]*rs*w[i];
}

// ---------------- dense SGEMM: C = A * B^T (+ addend) ----------------
// mode 0: C=g_q A=g_x   N=2048 | 1: C=g_k N=512 | 2: C=g_v N=512 | 3: C=g_h A=g_attn (+hidden)
__global__ __launch_bounds__(256) void sgemm_dense(
    const float* __restrict__ Bmat, const float* __restrict__ addend,
    int mode, int N)
{
    const float* A = (mode==3) ? g_attn : g_x;
    float* C = (mode==0) ? g_q : (mode==1) ? g_k : (mode==2) ? g_v : g_h;
    const int K = HID;
    __shared__ float As[BKK][BM];
    __shared__ float Bs[BKK][BN];
    int tid = threadIdx.x;
    int m0 = blockIdx.y*BM, n0 = blockIdx.x*BN;
    int tx = tid & 15, ty = tid >> 4;
    int r0 = tid >> 2, kc = (tid & 3)*4;
    int r1 = r0 + 64;
    const float* Ap0 = A    + (size_t)(m0+r0)*K + kc;
    const float* Ap1 = A    + (size_t)(m0+r1)*K + kc;
    const float* Bp0 = Bmat + (size_t)(n0+r0)*K + kc;
    const float* Bp1 = Bmat + (size_t)(n0+r1)*K + kc;
    float acc[8][8];
    #pragma unroll
    for (int i=0;i<8;i++)
        #pragma unroll
        for (int j=0;j<8;j++) acc[i][j]=0.f;
    for (int k0=0;k0<K;k0+=BKK){
        float4 a0 = *(const float4*)(Ap0 + k0);
        float4 a1 = *(const float4*)(Ap1 + k0);
        float4 b0 = *(const float4*)(Bp0 + k0);
        float4 b1 = *(const float4*)(Bp1 + k0);
        As[kc+0][r0]=a0.x; As[kc+1][r0]=a0.y; As[kc+2][r0]=a0.z; As[kc+3][r0]=a0.w;
        As[kc+0][r1]=a1.x; As[kc+1][r1]=a1.y; As[kc+2][r1]=a1.z; As[kc+3][r1]=a1.w;
        Bs[kc+0][r0]=b0.x; Bs[kc+1][r0]=b0.y; Bs[kc+2][r0]=b0.z; Bs[kc+3][r0]=b0.w;
        Bs[kc+0][r1]=b1.x; Bs[kc+1][r1]=b1.y; Bs[kc+2][r1]=b1.z; Bs[kc+3][r1]=b1.w;
        __syncthreads();
        #pragma unroll
        for (int k=0;k<BKK;k++){
            float a[8], b[8];
            *(float4*)&a[0] = *(const float4*)&As[k][ty*8];
            *(float4*)&a[4] = *(const float4*)&As[k][ty*8+4];
            *(float4*)&b[0] = *(const float4*)&Bs[k][tx*8];
            *(float4*)&b[4] = *(const float4*)&Bs[k][tx*8+4];
            #pragma unroll
            for (int i=0;i<8;i++)
                #pragma unroll
                for (int j=0;j<8;j++)
                    acc[i][j] += a[i]*b[j];
        }
        __syncthreads();
    }
    #pragma unroll
    for (int i=0;i<8;i++){
        int row = m0 + ty*8 + i;
        float* cp = C + (size_t)row*N + n0 + tx*8;
        if (addend){
            const float* ap = addend + (size_t)row*N + n0 + tx*8;
            #pragma unroll
            for (int j=0;j<8;j++) cp[j] = acc[i][j] + ap[j];
        } else {
            #pragma unroll
            for (int j=0;j<8;j++) cp[j] = acc[i][j];
        }
    }
}

// ---------------- RoPE (in-place on g_q / g_k) ----------------
__global__ void rope_kernel(int isK)
{
    int ncols = isK ? KVDIM : HID;
    int half  = ncols >> 1;                 // pairs per row
    int idx = blockIdx.x*256 + threadIdx.x;
    if (idx >= SEQ*half) return;
    int t = idx / half;
    int p = idx - t*half;
    int head = p >> 6;                      // 64 pairs per head
    int d = p & 63;
    float* buf = isK ? g_k : g_q;
    int c1 = head*HDIM + d;
    float inv = expf(-(float)d * (9.210340371976184f/64.f)); // 10000^(-d/64)
    float ang = (float)t * inv;
    float cs = cosf(ang), sn = sinf(ang);
    float* b1 = buf + (size_t)t*ncols + c1;
    float x1 = b1[0], x2 = b1[64];
    b1[0]  = x1*cs - x2*sn;
    b1[64] = x2*cs + x1*sn;
}

// ---------------- flash attention (causal, GQA 4:1) ----------------
// grid (S/64, NHEAD), 256 threads; thread = (row 0..63, quarter 0..3 of D)
__global__ __launch_bounds__(256,1) void flash_attn_kernel()
{
    __shared__ float KV[64][128];
    int qt = blockIdx.x, h = blockIdx.y;
    int kvh = h >> 2;
    int tid = threadIdx.x;
    int row = tid >> 2;
    int quar = tid & 3;
    int qrow = qt*64 + row;
    const float scale = 0.08838834764831845f;   // 1/sqrt(128)
    float qreg[32];
    const float4* qp = (const float4*)&g_q[(size_t)qrow*HID + h*HDIM + quar*32];
    #pragma unroll
    for (int i=0;i<8;i++){
        float4 v = qp[i];
        qreg[4*i+0]=v.x*scale; qreg[4*i+1]=v.y*scale;
        qreg[4*i+2]=v.z*scale; qreg[4*i+3]=v.w*scale;
    }
    float m = -1e30f, l = 0.f;
    float o[32];
    #pragma unroll
    for (int i=0;i<32;i++) o[i]=0.f;

    for (int kt = 0; kt <= qt; kt++){
        int k0 = kt*64;
        __syncthreads();
        {   // stage K tile
            const float4* src = (const float4*)&g_k[(size_t)(k0+row)*KVDIM + kvh*HDIM + quar*32];
            float4* dst = (float4*)&KV[row][quar*32];
            #pragma unroll
            for (int i=0;i<8;i++) dst[i]=src[i];
        }
        __syncthreads();
        float s[64];
        #pragma unroll
        for (int j=0;j<64;j++){
            const float4* kp = (const float4*)&KV[j][quar*32];
            float acc = 0.f;
            #pragma unroll
            for (int i=0;i<8;i++){
                float4 kv = kp[i];
                acc += qreg[4*i+0]*kv.x + qreg[4*i+1]*kv.y
                     + qreg[4*i+2]*kv.z + qreg[4*i+3]*kv.w;
            }
            acc += __shfl_xor_sync(0xffffffffu, acc, 1);
            acc += __shfl_xor_sync(0xffffffffu, acc, 2);
            s[j] = acc;
        }
        if (kt == qt){
            #pragma unroll
            for (int j=0;j<64;j++) if (k0+j > qrow) s[j] = -1e30f;
        }
        float nm = m;
        #pragma unroll
        for (int j=0;j<64;j++) nm = fmaxf(nm, s[j]);
        float corr = __expf(m - nm);
        float ls = 0.f;
        #pragma unroll
        for (int j=0;j<64;j++){ s[j] = __expf(s[j]-nm); ls += s[j]; }
        l = l*corr + ls;
        #pragma unroll
        for (int i=0;i<32;i++) o[i] *= corr;
        m = nm;
        __syncthreads();
        {   // stage V tile into the same buffer
            const float4* src = (const float4*)&g_v[(size_t)(k0+row)*KVDIM + kvh*HDIM + quar*32];
            float4* dst = (float4*)&KV[row][quar*32];
            #pragma unroll
            for (int i=0;i<8;i++) dst[i]=src[i];
        }
        __syncthreads();
        #pragma unroll
        for (int j=0;j<64;j++){
            float p = s[j];
            const float4* vp = (const float4*)&KV[j][quar*32];
            #pragma unroll
            for (int i=0;i<8;i++){
                float4 vv = vp[i];
                o[4*i+0]+=p*vv.x; o[4*i+1]+=p*vv.y;
                o[4*i+2]+=p*vv.z; o[4*i+3]+=p*vv.w;
            }
        }
    }
    float invl = 1.f/l;
    float4* op = (float4*)&g_attn[(size_t)qrow*HID + h*HDIM + quar*32];
    #pragma unroll
    for (int i=0;i<8;i++)
        op[i] = make_float4(o[4*i+0]*invl, o[4*i+1]*invl, o[4*i+2]*invl, o[4*i+3]*invl);
}

// ---------------- routing: softmax over 8 logits, top-2 ----------------
__global__ void route_kernel(const float* __restrict__ gate_w)
{
    int t = blockIdx.x;
    int wid = threadIdx.x >> 5, lane = threadIdx.x & 31;
    __shared__ float slog[NEXP];
    const float* x  = g_x2 + (size_t)t*HID;
    const float* gw = gate_w + (size_t)wid*HID;
    float acc = 0.f;
    for (int i = lane; i < HID; i += 32) acc += x[i]*gw[i];
    #pragma unroll
    for (int o=16;o;o>>=1) acc += __shfl_xor_sync(0xffffffffu, acc, o);
    if (lane == 0) slog[wid] = acc;
    __syncthreads();
    if (threadIdx.x == 0){
        float mx = slog[0];
        for (int e=1;e<NEXP;e++) mx = fmaxf(mx, slog[e]);
        float p[NEXP]; float se = 0.f;
        for (int e=0;e<NEXP;e++){ p[e] = expf(slog[e]-mx); se += p[e]; }
        float inv = 1.f/se;
        for (int e=0;e<NEXP;e++) p[e] *= inv;
        int i1 = 0;
        for (int e=1;e<NEXP;e++) if (p[e] > p[i1]) i1 = e;
        int i2 = (i1==0) ? 1 : 0;
        for (int e=0;e<NEXP;e++) if (e!=i1 && p[e] > p[i2]) i2 = e;
        float v1 = p[i1], v2 = p[i2], s2 = 1.f/(v1+v2);
        g_topi[2*t]=i1; g_topi[2*t+1]=i2;
        g_topv[2*t]=v1*s2; g_topv[2*t+1]=v2*s2;
    }
}

// ---------------- deterministic per-expert token lists (one block) ----------------
__global__ void assign_kernel()
{
    __shared__ int scn[256];
    int tid = threadIdx.x;
    int base = 0;
    for (int e=0;e<NEXP;e++){
        int fl[8]; float fw[8];
        int local = 0;
        #pragma unroll
        for (int j=0;j<8;j++){
            int t = tid*8 + j;
            int a = g_topi[2*t], b = g_topi[2*t+1];
            float w = 0.f; int f = 0;
            if (a==e){ w += g_topv[2*t];   f = 1; }
            if (b==e){ w += g_topv[2*t+1]; f = 1; }
            fl[j]=f; fw[j]=w; local += f;
        }
        scn[tid]=local;
        __syncthreads();
        for (int d=1; d<256; d<<=1){          // Kogge-Stone inclusive scan
            int v = (tid>=d) ? scn[tid-d] : 0;
            __syncthreads();
            scn[tid] += v;
            __syncthreads();
        }
        int pos   = base + scn[tid] - local;  // exclusive prefix
        int total = scn[255];
        #pragma unroll
        for (int j=0;j<8;j++){
            if (fl[j]){ g_tok[pos]=tid*8+j; g_wgt[pos]=fw[j]; pos++; }
        }
        if (tid==0){ g_cnt[e]=total; g_off[e]=base; }
        base += total;
        __syncthreads();
    }
}

// ---------------- MoE up/gate projections with row gather ----------------
// which 0: C=g_t1 (w1) | 1: C=g_t3 (w3)
__global__ __launch_bounds__(256) void sgemm_moe_in(const float* __restrict__ Wbase, int which)
{
    int z = blockIdx.z;
    int cnt = g_cnt[z];
    int m0 = blockIdx.y*BM;
    if (m0 >= cnt) return;
    int off = g_off[z];
    const float* Bmat = Wbase + (size_t)z*FFD*HID;     // [FFD, HID]
    float* C = which ? g_t3 : g_t1;
    const int K = HID;
    __shared__ float As[BKK][BM];
    __shared__ float Bs[BKK][BN];
    int tid = threadIdx.x;
    int n0 = blockIdx.x*BN;
    int tx = tid & 15, ty = tid >> 4;
    int r0 = tid >> 2, kc = (tid & 3)*4;
    int r1 = r0 + 64;
    int gi0 = off + min(m0+r0, cnt-1);                 // clamped: garbage rows never stored
    int gi1 = off + min(m0+r1, cnt-1);
    const float* Ap0 = g_x2 + (size_t)g_tok[gi0]*K + kc;
    const float* Ap1 = g_x2 + (size_t)g_tok[gi1]*K + kc;
    const float* Bp0 = Bmat + (size_t)(n0+r0)*K + kc;
    const float* Bp1 = Bmat + (size_t)(n0+r1)*K + kc;
    float acc[8][8];
    #pragma unroll
    for (int i=0;i<8;i++)
        #pragma unroll
        for (int j=0;j<8;j++) acc[i][j]=0.f;
    for (int k0=0;k0<K;k0+=BKK){
        float4 a0 = *(const float4*)(Ap0 + k0);
        float4 a1 = *(const float4*)(Ap1 + k0);
        float4 b0 = *(const float4*)(Bp0 + k0);
        float4 b1 = *(const float4*)(Bp1 + k0);
        As[kc+0][r0]=a0.x; As[kc+1][r0]=a0.y; As[kc+2][r0]=a0.z; As[kc+3][r0]=a0.w;
        As[kc+0][r1]=a1.x; As[kc+1][r1]=a1.y; As[kc+2][r1]=a1.z; As[kc+3][r1]=a1.w;
        Bs[kc+0][r0]=b0.x; Bs[kc+1][r0]=b0.y; Bs[kc+2][r0]=b0.z; Bs[kc+3][r0]=b0.w;
        Bs[kc+0][r1]=b1.x; Bs[kc+1][r1]=b1.y; Bs[kc+2][r1]=b1.z; Bs[kc+3][r1]=b1.w;
        __syncthreads();
        #pragma unroll
        for (int k=0;k<BKK;k++){
            float a[8], b[8];
            *(float4*)&a[0] = *(const float4*)&As[k][ty*8];
            *(float4*)&a[4] = *(const float4*)&As[k][ty*8+4];
            *(float4*)&b[0] = *(const float4*)&Bs[k][tx*8];
            *(float4*)&b[4] = *(const float4*)&Bs[k][tx*8+4];
            #pragma unroll
            for (int i=0;i<8;i++)
                #pragma unroll
                for (int j=0;j<8;j++)
                    acc[i][j] += a[i]*b[j];
        }
        __syncthreads();
    }
    #pragma unroll
    for (int i=0;i<8;i++){
        int r = m0 + ty*8 + i;
        if (r < cnt){
            float* cp = C + (size_t)(off+r)*FFD + n0 + tx*8;
            #pragma unroll
            for (int j=0;j<8;j++) cp[j] = acc[i][j];
        }
    }
}

// ---------------- swiglu: g_t1 = silu(g_t1)*g_t3 ----------------
__global__ void swiglu_kernel()
{
    size_t i = (size_t)blockIdx.x*256 + threadIdx.x;
    float a = g_t1[i], b = g_t3[i];
    float sg = 1.f/(1.f + __expf(-a));
    g_t1[i] = a*sg*b;
}

// ---------------- base: out = h ----------------
__global__ void copy_h_kernel(float* __restrict__ out)
{
    int i = blockIdx.x*256 + threadIdx.x;
    out[i] = g_h[i];
}

// ---------------- MoE down projection with weighted atomic scatter ----------------
__global__ __launch_bounds__(256) void sgemm_moe_out(const float* __restrict__ W2, float* __restrict__ out)
{
    int z = blockIdx.z;
    int cnt = g_cnt[z];
    int m0 = blockIdx.y*BM;
    if (m0 >= cnt) return;
    int off = g_off[z];
    const float* Bmat = W2 + (size_t)z*HID*FFD;        // [HID, FFD]
    const int K = FFD;
    const int N = HID;
    __shared__ float As[BKK][BM];
    __shared__ float Bs[BKK][BN];
    int tid = threadIdx.x;
    int n0 = blockIdx.x*BN;
    int tx = tid & 15, ty = tid >> 4;
    int r0 = tid >> 2, kc = (tid & 3)*4;
    int r1 = r0 + 64;
    int ai0 = off + min(m0+r0, cnt-1);                 // clamped rows (never stored)
    int ai1 = off + min(m0+r1, cnt-1);
    const float* Ap0 = g_t1 + (size_t)ai0*K + kc;
    const float* Ap1 = g_t1 + (size_t)ai1*K + kc;
    const float* Bp0 = Bmat + (size_t)(n0+r0)*K + kc;
    const float* Bp1 = Bmat + (size_t)(n0+r1)*K + kc;
    float acc[8][8];
    #pragma unroll
    for (int i=0;i<8;i++)
        #pragma unroll
        for (int j=0;j<8;j++) acc[i][j]=0.f;
    for (int k0=0;k0<K;k0+=BKK){
        float4 a0 = *(const float4*)(Ap0 + k0);
        float4 a1 = *(const float4*)(Ap1 + k0);
        float4 b0 = *(const float4*)(Bp0 + k0);
        float4 b1 = *(const float4*)(Bp1 + k0);
        As[kc+0][r0]=a0.x; As[kc+1][r0]=a0.y; As[kc+2][r0]=a0.z; As[kc+3][r0]=a0.w;
        As[kc+0][r1]=a1.x; As[kc+1][r1]=a1.y; As[kc+2][r1]=a1.z; As[kc+3][r1]=a1.w;
        Bs[kc+0][r0]=b0.x; Bs[kc+1][r0]=b0.y; Bs[kc+2][r0]=b0.z; Bs[kc+3][r0]=b0.w;
        Bs[kc+0][r1]=b1.x; Bs[kc+1][r1]=b1.y; Bs[kc+2][r1]=b1.z; Bs[kc+3][r1]=b1.w;
        __syncthreads();
        #pragma unroll
        for (int k=0;k<BKK;k++){
            float a[8], b[8];
            *(float4*)&a[0] = *(const float4*)&As[k][ty*8];
            *(float4*)&a[4] = *(const float4*)&As[k][ty*8+4];
            *(float4*)&b[0] = *(const float4*)&Bs[k][tx*8];
            *(float4*)&b[4] = *(const float4*)&Bs[k][tx*8+4];
            #pragma unroll
            for (int i=0;i<8;i++)
                #pragma unroll
                for (int j=0;j<8;j++)
                    acc[i][j] += a[i]*b[j];
        }
        __syncthreads();
    }
    #pragma unroll
    for (int i=0;i<8;i++){
        int r = m0 + ty*8 + i;
        if (r < cnt){
            int tok = g_tok[off+r];
            float w = g_wgt[off+r];
            float* op = out + (size_t)tok*HID + n0 + tx*8;
            #pragma unroll
            for (int j=0;j<8;j++) atomicAdd(&op[j], w*acc[i][j]);
        }
    }
}

// ---------------- launch ----------------
extern "C" void kernel_launch(void* const* d_in, const int* in_sizes, int n_in,
                              void* d_out, int out_size)
{
    (void)in_sizes; (void)n_in; (void)out_size;
    const float* hidden = (const float*)d_in[0];
    const float* ln1_w  = (const float*)d_in[1];
    const float* ln2_w  = (const float*)d_in[2];
    const float* q_w    = (const float*)d_in[3];
    const float* k_w    = (const float*)d_in[4];
    const float* v_w    = (const float*)d_in[5];
    const float* o_w    = (const float*)d_in[6];
    const float* gate_w = (const float*)d_in[7];
    const float* w1     = (const float*)d_in[8];   // setup_inputs dict order: w1, w3, w2
    const float* w3     = (const float*)d_in[9];
    const float* w2     = (const float*)d_in[10];
    float* out = (float*)d_out;

    rmsnorm_kernel<<<SEQ,256>>>(hidden, ln1_w, 0);
    sgemm_dense<<<dim3(HID/BN,   SEQ/BM),256>>>(q_w, nullptr, 0, HID);
    sgemm_dense<<<dim3(KVDIM/BN, SEQ/BM),256>>>(k_w, nullptr, 1, KVDIM);
    sgemm_dense<<<dim3(KVDIM/BN, SEQ/BM),256>>>(v_w, nullptr, 2, KVDIM);
    rope_kernel<<<(SEQ*(HID/2))/256,  256>>>(0);
    rope_kernel<<<(SEQ*(KVDIM/2))/256,256>>>(1);
    flash_attn_kernel<<<dim3(SEQ/64, NHEAD),256>>>();
    sgemm_dense<<<dim3(HID/BN, SEQ/BM),256>>>(o_w, hidden, 3, HID);   // g_h = attn@o_w^T + hidden
    rmsnorm_kernel<<<SEQ,256>>>(hidden, ln2_w, 1);
    route_kernel<<<SEQ,256>>>(gate_w);
    assign_kernel<<<1,256>>>();
    sgemm_moe_in<<<dim3(FFD/BN, SEQ/BM, NEXP),256>>>(w1, 0);
    sgemm_moe_in<<<dim3(FFD/BN, SEQ/BM, NEXP),256>>>(w3, 1);
    swiglu_kernel<<<(NASSIGN*FFD)/256,256>>>();
    copy_h_kernel<<<(SEQ*HID)/256,256>>>(out);
    sgemm_moe_out<<<dim3(HID/BN, SEQ/BM, NEXP),256>>>(w2, out);
}

// round 8
// speedup vs baseline: 1.2722x; 1.2722x over previous
#include <cuda_runtime.h>
#include <cuda_bf16.h>
#include <cstdint>
#include <math.h>

#define SEQ   2048
#define HID   2048
#define HDIM  128
#define NHEAD 16
#define KVDIM 512
#define FFD   4096
#define NEXP  8
#define NASSIGN (2*SEQ)
#define PITCH 40

typedef __nv_bfloat16 bf16;
typedef unsigned int u32;

// ---------------- scratch (device globals: allocation-free rule) ----------------
__device__ float g_q[SEQ*HID];
__device__ float g_k[SEQ*KVDIM];
__device__ float g_v[SEQ*KVDIM];
__device__ float g_h[SEQ*HID];
__device__ float g_x2[SEQ*HID];
__device__ float g_t1[NASSIGN*FFD];
__device__ float g_t3[NASSIGN*FFD];

__device__ bf16  g_xhi[SEQ*HID];
__device__ bf16  g_xlo[SEQ*HID];
__device__ bf16  g_x2hi[SEQ*HID];
__device__ bf16  g_x2lo[SEQ*HID];
__device__ bf16  g_ahi[SEQ*HID];
__device__ bf16  g_alo[SEQ*HID];
__device__ bf16  g_t1hi[NASSIGN*FFD];
__device__ bf16  g_t1lo[NASSIGN*FFD];

__device__ bf16  g_qwh[HID*HID];
__device__ bf16  g_qwl[HID*HID];
__device__ bf16  g_kwh[KVDIM*HID];
__device__ bf16  g_kwl[KVDIM*HID];
__device__ bf16  g_vwh[KVDIM*HID];
__device__ bf16  g_vwl[KVDIM*HID];
__device__ bf16  g_owh[HID*HID];
__device__ bf16  g_owl[HID*HID];
__device__ bf16  g_w1h[NEXP*FFD*HID];
__device__ bf16  g_w1l[NEXP*FFD*HID];
__device__ bf16  g_w3h[NEXP*FFD*HID];
__device__ bf16  g_w3l[NEXP*FFD*HID];
__device__ bf16  g_w2h[NEXP*HID*FFD];
__device__ bf16  g_w2l[NEXP*HID*FFD];

__device__ int   g_topi[SEQ*2];
__device__ float g_topv[SEQ*2];
__device__ int   g_tok[NASSIGN];
__device__ float g_wgt[NASSIGN];
__device__ int   g_cnt[NEXP];
__device__ int   g_off[NEXP];

// ---------------- helpers ----------------
__device__ __forceinline__ void split2(float v, bf16& h, bf16& l){
    h = __float2bfloat16(v);
    l = __float2bfloat16(v - __bfloat162float(h));
}

__device__ __forceinline__ void ldsm4(u32& r0, u32& r1, u32& r2, u32& r3, const bf16* p){
    u32 a = (u32)__cvta_generic_to_shared(p);
    asm volatile("ldmatrix.sync.aligned.m8n8.x4.shared.b16 {%0,%1,%2,%3}, [%4];"
        : "=r"(r0), "=r"(r1), "=r"(r2), "=r"(r3) : "r"(a));
}

__device__ __forceinline__ void mma_bf16(float* c, const u32* a, const u32* b){
    asm volatile("mma.sync.aligned.m16n8k16.row.col.f32.bf16.bf16.f32 "
        "{%0,%1,%2,%3}, {%4,%5,%6,%7}, {%8,%9}, {%0,%1,%2,%3};"
        : "+f"(c[0]), "+f"(c[1]), "+f"(c[2]), "+f"(c[3])
        : "r"(a[0]), "r"(a[1]), "r"(a[2]), "r"(a[3]), "r"(b[0]), "r"(b[1]));
}

// weight-pair selector (device side)
__device__ __forceinline__ void sel_w(int s, const bf16*& hi, const bf16*& lo){
    switch (s){
        case 0: hi = g_qwh; lo = g_qwl; break;
        case 1: hi = g_kwh; lo = g_kwl; break;
        case 2: hi = g_vwh; lo = g_vwl; break;
        case 3: hi = g_owh; lo = g_owl; break;
        case 4: hi = g_w1h; lo = g_w1l; break;
        case 5: hi = g_w3h; lo = g_w3l; break;
        default: hi = g_w2h; lo = g_w2l; break;
    }
}

__device__ __forceinline__ void sel_a(int s, const bf16*& hi, const bf16*& lo){
    switch (s){
        case 0: hi = g_xhi;  lo = g_xlo;  break;
        case 1: hi = g_ahi;  lo = g_alo;  break;
        case 2: hi = g_x2hi; lo = g_x2lo; break;
        default: hi = g_t1hi; lo = g_t1lo; break;
    }
}

__device__ __forceinline__ float* sel_c(int s, float* ext){
    switch (s){
        case 0: return g_q;
        case 1: return g_k;
        case 2: return g_v;
        case 3: return g_h;
        case 4: return g_t1;
        case 5: return g_t3;
        default: return ext;
    }
}

// ---------------- fp32 -> bf16 hi/lo conversion (dst picked by selector) ----------------
__global__ void cvt_kernel(const float* __restrict__ src, int wsel, size_t n)
{
    const bf16 *hic, *loc;
    sel_w(wsel, hic, loc);
    bf16* hi = (bf16*)hic;
    bf16* lo = (bf16*)loc;
    size_t i = ((size_t)blockIdx.x*256 + threadIdx.x)*4;
    if (i >= n) return;
    float4 v = *(const float4*)(src + i);
    bf16 h0,l0,h1,l1,h2,l2,h3,l3;
    split2(v.x,h0,l0); split2(v.y,h1,l1); split2(v.z,h2,l2); split2(v.w,h3,l3);
    __nv_bfloat162 ph0; ph0.x=h0; ph0.y=h1;
    __nv_bfloat162 ph1; ph1.x=h2; ph1.y=h3;
    __nv_bfloat162 pl0; pl0.x=l0; pl0.y=l1;
    __nv_bfloat162 pl1; pl1.x=l2; pl1.y=l3;
    *(__nv_bfloat162*)(hi+i)   = ph0;
    *(__nv_bfloat162*)(hi+i+2) = ph1;
    *(__nv_bfloat162*)(lo+i)   = pl0;
    *(__nv_bfloat162*)(lo+i+2) = pl1;
}

// ---------------- rmsnorm ----------------
// mode 0: in = external `hidden` ptr -> g_xhi/g_xlo
// mode 1: in = g_h (device global, resolved HERE, not via host arg) -> g_x2hi/g_x2lo + g_x2
__global__ void rmsnorm_kernel(const float* __restrict__ in_ext, const float* __restrict__ w, int mode)
{
    const float* in = mode ? (const float*)g_h : in_ext;
    bf16* hi = mode ? g_x2hi : g_xhi;
    bf16* lo = mode ? g_x2lo : g_xlo;
    float* f32out = mode ? g_x2 : (float*)0;
    int row = blockIdx.x;
    const float* x = in + (size_t)row*HID;
    __shared__ float red[256];
    float ss = 0.f;
    for (int i = threadIdx.x; i < HID; i += 256) { float v = x[i]; ss += v*v; }
    red[threadIdx.x] = ss; __syncthreads();
    for (int s = 128; s > 0; s >>= 1) {
        if (threadIdx.x < s) red[threadIdx.x] += red[threadIdx.x+s];
        __syncthreads();
    }
    float rs = rsqrtf(red[0]/(float)HID + 1e-5f);
    size_t base = (size_t)row*HID;
    for (int i = threadIdx.x; i < HID; i += 256){
        float v = x[i]*rs*w[i];
        bf16 h,l; split2(v,h,l);
        hi[base+i]=h; lo[base+i]=l;
        if (f32out) f32out[base+i]=v;
    }
}

// ---------------- MMA GEMM: C = A * B^T (bf16x3 split, fp32 accum) ----------------
// mode 0: dense store | 1: dense + addend | 2: moe gather-in | 3: moe scatter-out
__global__ __launch_bounds__(256,1) void mma_gemm(
    int asel, int bsel, int csel, float* __restrict__ Cext,
    const float* __restrict__ addend, int K, int N, int mode)
{
    __shared__ __align__(16) bf16 sAhi[128][PITCH];
    __shared__ __align__(16) bf16 sAlo[128][PITCH];
    __shared__ __align__(16) bf16 sBhi[128][PITCH];
    __shared__ __align__(16) bf16 sBlo[128][PITCH];

    const bf16 *Ahi, *Alo, *Bhi, *Blo;
    sel_a(asel, Ahi, Alo);
    sel_w(bsel, Bhi, Blo);
    float* C = sel_c(csel, Cext);

    int tid = threadIdx.x, lane = tid & 31, wid = tid >> 5;
    int m0 = blockIdx.y*128, n0 = blockIdx.x*128;
    int cnt = 0, off = 0;
    if (mode >= 2){
        int z = blockIdx.z;
        cnt = g_cnt[z]; off = g_off[z];
        if (m0 >= cnt) return;
        Bhi += (size_t)z*N*K; Blo += (size_t)z*N*K;
    }

    int sr = tid >> 1, sh = (tid & 1)*16;
    int arow;
    if (mode == 2)      arow = g_tok[off + min(m0+sr, cnt-1)];
    else if (mode == 3) arow = off + min(m0+sr, cnt-1);
    else                arow = m0 + sr;
    const bf16* pAh = Ahi + (size_t)arow*K + sh;
    const bf16* pAl = Alo + (size_t)arow*K + sh;
    const bf16* pBh = Bhi + (size_t)(n0+sr)*K + sh;
    const bf16* pBl = Blo + (size_t)(n0+sr)*K + sh;

    int wm = (wid & 1)*64, wn = (wid >> 1)*32;
    float acc[4][4][4];
    #pragma unroll
    for (int mi=0;mi<4;mi++)
        #pragma unroll
        for (int ni=0;ni<4;ni++)
            #pragma unroll
            for (int r=0;r<4;r++) acc[mi][ni][r]=0.f;

    for (int k0=0; k0<K; k0+=32){
        *(uint4*)&sAhi[sr][sh]   = *(const uint4*)(pAh+k0);
        *(uint4*)&sAhi[sr][sh+8] = *(const uint4*)(pAh+k0+8);
        *(uint4*)&sAlo[sr][sh]   = *(const uint4*)(pAl+k0);
        *(uint4*)&sAlo[sr][sh+8] = *(const uint4*)(pAl+k0+8);
        *(uint4*)&sBhi[sr][sh]   = *(const uint4*)(pBh+k0);
        *(uint4*)&sBhi[sr][sh+8] = *(const uint4*)(pBh+k0+8);
        *(uint4*)&sBlo[sr][sh]   = *(const uint4*)(pBl+k0);
        *(uint4*)&sBlo[sr][sh+8] = *(const uint4*)(pBl+k0+8);
        __syncthreads();
        #pragma unroll
        for (int ks=0; ks<32; ks+=16){
            u32 fah[4][4], fal[4][4], fbh[4][2], fbl[4][2];
            int ar = lane & 15;
            int ac = ks + ((lane >> 4) << 3);
            #pragma unroll
            for (int mi=0;mi<4;mi++){
                ldsm4(fah[mi][0],fah[mi][1],fah[mi][2],fah[mi][3], &sAhi[wm+mi*16+ar][ac]);
                ldsm4(fal[mi][0],fal[mi][1],fal[mi][2],fal[mi][3], &sAlo[wm+mi*16+ar][ac]);
            }
            int br = ((lane >> 4) << 3) + (lane & 7);
            int bc = ks + (((lane >> 3) & 1) << 3);
            #pragma unroll
            for (int np=0;np<2;np++){
                ldsm4(fbh[np*2][0],fbh[np*2][1],fbh[np*2+1][0],fbh[np*2+1][1], &sBhi[wn+np*16+br][bc]);
                ldsm4(fbl[np*2][0],fbl[np*2][1],fbl[np*2+1][0],fbl[np*2+1][1], &sBlo[wn+np*16+br][bc]);
            }
            #pragma unroll
            for (int mi=0;mi<4;mi++)
                #pragma unroll
                for (int ni=0;ni<4;ni++){
                    mma_bf16(acc[mi][ni], fah[mi], fbh[ni]);
                    mma_bf16(acc[mi][ni], fah[mi], fbl[ni]);
                    mma_bf16(acc[mi][ni], fal[mi], fbh[ni]);
                }
        }
        __syncthreads();
    }

    int tr = lane >> 2, tc = (lane & 3)*2;
    if (mode <= 1){
        #pragma unroll
        for (int mi=0;mi<4;mi++)
            #pragma unroll
            for (int hh=0;hh<2;hh++){
                int row = m0 + wm + mi*16 + tr + hh*8;
                float* cp = C + (size_t)row*N + n0 + wn;
                #pragma unroll
                for (int ni=0;ni<4;ni++){
                    float v0 = acc[mi][ni][hh*2], v1 = acc[mi][ni][hh*2+1];
                    if (mode==1){
                        const float* ap = addend + (size_t)row*N + n0 + wn;
                        v0 += ap[ni*8+tc]; v1 += ap[ni*8+tc+1];
                    }
                    cp[ni*8+tc] = v0; cp[ni*8+tc+1] = v1;
                }
            }
    } else if (mode == 2){
        #pragma unroll
        for (int mi=0;mi<4;mi++)
            #pragma unroll
            for (int hh=0;hh<2;hh++){
                int slot = m0 + wm + mi*16 + tr + hh*8;
                if (slot < cnt){
                    float* cp = C + (size_t)(off+slot)*N + n0 + wn;
                    #pragma unroll
                    for (int ni=0;ni<4;ni++){
                        cp[ni*8+tc]   = acc[mi][ni][hh*2];
                        cp[ni*8+tc+1] = acc[mi][ni][hh*2+1];
                    }
                }
            }
    } else {
        #pragma unroll
        for (int mi=0;mi<4;mi++)
            #pragma unroll
            for (int hh=0;hh<2;hh++){
                int slot = m0 + wm + mi*16 + tr + hh*8;
                if (slot < cnt){
                    int tok = g_tok[off+slot];
                    float w = g_wgt[off+slot];
                    float* op = C + (size_t)tok*HID + n0 + wn;
                    #pragma unroll
                    for (int ni=0;ni<4;ni++){
                        atomicAdd(&op[ni*8+tc],   w*acc[mi][ni][hh*2]);
                        atomicAdd(&op[ni*8+tc+1], w*acc[mi][ni][hh*2+1]);
                    }
                }
            }
    }
}

// ---------------- RoPE (in-place on g_q / g_k) ----------------
__global__ void rope_kernel(int isK)
{
    int ncols = isK ? KVDIM : HID;
    int half  = ncols >> 1;
    int idx = blockIdx.x*256 + threadIdx.x;
    if (idx >= SEQ*half) return;
    int t = idx / half;
    int p = idx - t*half;
    int head = p >> 6;
    int d = p & 63;
    float* buf = isK ? g_k : g_q;
    int c1 = head*HDIM + d;
    float inv = expf(-(float)d * (9.210340371976184f/64.f));
    float ang = (float)t * inv;
    float cs = cosf(ang), sn = sinf(ang);
    float* b1 = buf + (size_t)t*ncols + c1;
    float x1 = b1[0], x2 = b1[64];
    b1[0]  = x1*cs - x2*sn;
    b1[64] = x2*cs + x1*sn;
}

// ---------------- flash attention (causal, GQA 4:1), writes bf16 hi/lo ----------------
__global__ __launch_bounds__(256,1) void flash_attn_kernel()
{
    __shared__ float KV[64][128];
    int qt = blockIdx.x, h = blockIdx.y;
    int kvh = h >> 2;
    int tid = threadIdx.x;
    int row = tid >> 2;
    int quar = tid & 3;
    int qrow = qt*64 + row;
    const float scale = 0.08838834764831845f;
    float qreg[32];
    const float4* qp = (const float4*)&g_q[(size_t)qrow*HID + h*HDIM + quar*32];
    #pragma unroll
    for (int i=0;i<8;i++){
        float4 v = qp[i];
        qreg[4*i+0]=v.x*scale; qreg[4*i+1]=v.y*scale;
        qreg[4*i+2]=v.z*scale; qreg[4*i+3]=v.w*scale;
    }
    float m = -1e30f, l = 0.f;
    float o[32];
    #pragma unroll
    for (int i=0;i<32;i++) o[i]=0.f;

    for (int kt = 0; kt <= qt; kt++){
        int k0 = kt*64;
        __syncthreads();
        {
            const float4* src = (const float4*)&g_k[(size_t)(k0+row)*KVDIM + kvh*HDIM + quar*32];
            float4* dst = (float4*)&KV[row][quar*32];
            #pragma unroll
            for (int i=0;i<8;i++) dst[i]=src[i];
        }
        __syncthreads();
        float s[64];
        #pragma unroll
        for (int j=0;j<64;j++){
            const float4* kp = (const float4*)&KV[j][quar*32];
            float acc = 0.f;
            #pragma unroll
            for (int i=0;i<8;i++){
                float4 kv = kp[i];
                acc += qreg[4*i+0]*kv.x + qreg[4*i+1]*kv.y
                     + qreg[4*i+2]*kv.z + qreg[4*i+3]*kv.w;
            }
            acc += __shfl_xor_sync(0xffffffffu, acc, 1);
            acc += __shfl_xor_sync(0xffffffffu, acc, 2);
            s[j] = acc;
        }
        if (kt == qt){
            #pragma unroll
            for (int j=0;j<64;j++) if (k0+j > qrow) s[j] = -1e30f;
        }
        float nm = m;
        #pragma unroll
        for (int j=0;j<64;j++) nm = fmaxf(nm, s[j]);
        float corr = __expf(m - nm);
        float ls = 0.f;
        #pragma unroll
        for (int j=0;j<64;j++){ s[j] = __expf(s[j]-nm); ls += s[j]; }
        l = l*corr + ls;
        #pragma unroll
        for (int i=0;i<32;i++) o[i] *= corr;
        m = nm;
        __syncthreads();
        {
            const float4* src = (const float4*)&g_v[(size_t)(k0+row)*KVDIM + kvh*HDIM + quar*32];
            float4* dst = (float4*)&KV[row][quar*32];
            #pragma unroll
            for (int i=0;i<8;i++) dst[i]=src[i];
        }
        __syncthreads();
        #pragma unroll
        for (int j=0;j<64;j++){
            float p = s[j];
            const float4* vp = (const float4*)&KV[j][quar*32];
            #pragma unroll
            for (int i=0;i<8;i++){
                float4 vv = vp[i];
                o[4*i+0]+=p*vv.x; o[4*i+1]+=p*vv.y;
                o[4*i+2]+=p*vv.z; o[4*i+3]+=p*vv.w;
            }
        }
    }
    float invl = 1.f/l;
    size_t base = (size_t)qrow*HID + h*HDIM + quar*32;
    #pragma unroll
    for (int i=0;i<32;i+=2){
        float v0 = o[i]*invl, v1 = o[i+1]*invl;
        bf16 h0,l0,h1,l1;
        split2(v0,h0,l0); split2(v1,h1,l1);
        __nv_bfloat162 ph; ph.x=h0; ph.y=h1;
        __nv_bfloat162 pl; pl.x=l0; pl.y=l1;
        *(__nv_bfloat162*)(g_ahi+base+i) = ph;
        *(__nv_bfloat162*)(g_alo+base+i) = pl;
    }
}

// ---------------- routing ----------------
__global__ void route_kernel(const float* __restrict__ gate_w)
{
    int t = blockIdx.x;
    int wid = threadIdx.x >> 5, lane = threadIdx.x & 31;
    __shared__ float slog[NEXP];
    const float* x  = g_x2 + (size_t)t*HID;
    const float* gw = gate_w + (size_t)wid*HID;
    float acc = 0.f;
    for (int i = lane; i < HID; i += 32) acc += x[i]*gw[i];
    #pragma unroll
    for (int o=16;o;o>>=1) acc += __shfl_xor_sync(0xffffffffu, acc, o);
    if (lane == 0) slog[wid] = acc;
    __syncthreads();
    if (threadIdx.x == 0){
        float mx = slog[0];
        for (int e=1;e<NEXP;e++) mx = fmaxf(mx, slog[e]);
        float p[NEXP]; float se = 0.f;
        for (int e=0;e<NEXP;e++){ p[e] = expf(slog[e]-mx); se += p[e]; }
        float inv = 1.f/se;
        for (int e=0;e<NEXP;e++) p[e] *= inv;
        int i1 = 0;
        for (int e=1;e<NEXP;e++) if (p[e] > p[i1]) i1 = e;
        int i2 = (i1==0) ? 1 : 0;
        for (int e=0;e<NEXP;e++) if (e!=i1 && p[e] > p[i2]) i2 = e;
        float v1 = p[i1], v2 = p[i2], s2 = 1.f/(v1+v2);
        g_topi[2*t]=i1; g_topi[2*t+1]=i2;
        g_topv[2*t]=v1*s2; g_topv[2*t+1]=v2*s2;
    }
}

// ---------------- deterministic per-expert token lists ----------------
__global__ void assign_kernel()
{
    __shared__ int scn[256];
    int tid = threadIdx.x;
    int base = 0;
    for (int e=0;e<NEXP;e++){
        int fl[8]; float fw[8];
        int local = 0;
        #pragma unroll
        for (int j=0;j<8;j++){
            int t = tid*8 + j;
            int a = g_topi[2*t], b = g_topi[2*t+1];
            float w = 0.f; int f = 0;
            if (a==e){ w += g_topv[2*t];   f = 1; }
            if (b==e){ w += g_topv[2*t+1]; f = 1; }
            fl[j]=f; fw[j]=w; local += f;
        }
        scn[tid]=local;
        __syncthreads();
        for (int d=1; d<256; d<<=1){
            int v = (tid>=d) ? scn[tid-d] : 0;
            __syncthreads();
            scn[tid] += v;
            __syncthreads();
        }
        int pos   = base + scn[tid] - local;
        int total = scn[255];
        #pragma unroll
        for (int j=0;j<8;j++){
            if (fl[j]){ g_tok[pos]=tid*8+j; g_wgt[pos]=fw[j]; pos++; }
        }
        if (tid==0){ g_cnt[e]=total; g_off[e]=base; }
        base += total;
        __syncthreads();
    }
}

// ---------------- swiglu: t1 = silu(t1)*t3, write bf16 hi/lo ----------------
__global__ void swiglu_kernel()
{
    size_t i = ((size_t)blockIdx.x*256 + threadIdx.x)*4;
    float4 a = *(const float4*)(g_t1+i);
    float4 b = *(const float4*)(g_t3+i);
    float v0 = a.x*b.x/(1.f+__expf(-a.x));
    float v1 = a.y*b.y/(1.f+__expf(-a.y));
    float v2 = a.z*b.z/(1.f+__expf(-a.z));
    float v3 = a.w*b.w/(1.f+__expf(-a.w));
    bf16 h0,l0,h1,l1,h2,l2,h3,l3;
    split2(v0,h0,l0); split2(v1,h1,l1); split2(v2,h2,l2); split2(v3,h3,l3);
    __nv_bfloat162 ph0; ph0.x=h0; ph0.y=h1;
    __nv_bfloat162 ph1; ph1.x=h2; ph1.y=h3;
    __nv_bfloat162 pl0; pl0.x=l0; pl0.y=l1;
    __nv_bfloat162 pl1; pl1.x=l2; pl1.y=l3;
    *(__nv_bfloat162*)(g_t1hi+i)   = ph0;
    *(__nv_bfloat162*)(g_t1hi+i+2) = ph1;
    *(__nv_bfloat162*)(g_t1lo+i)   = pl0;
    *(__nv_bfloat162*)(g_t1lo+i+2) = pl1;
}

// ---------------- base: out = h ----------------
__global__ void copy_h_kernel(float* __restrict__ out)
{
    int i = blockIdx.x*256 + threadIdx.x;
    out[i] = g_h[i];
}

// ---------------- launch ----------------
extern "C" void kernel_launch(void* const* d_in, const int* in_sizes, int n_in,
                              void* d_out, int out_size)
{
    (void)in_sizes; (void)n_in; (void)out_size;
    const float* hidden = (const float*)d_in[0];
    const float* ln1_w  = (const float*)d_in[1];
    const float* ln2_w  = (const float*)d_in[2];
    const float* q_w    = (const float*)d_in[3];
    const float* k_w    = (const float*)d_in[4];
    const float* v_w    = (const float*)d_in[5];
    const float* o_w    = (const float*)d_in[6];
    const float* gate_w = (const float*)d_in[7];
    const float* w1     = (const float*)d_in[8];
    const float* w3     = (const float*)d_in[9];
    const float* w2     = (const float*)d_in[10];
    float* out = (float*)d_out;

    // weight conversion fp32 -> bf16 hi/lo (selectors: 0 q,1 k,2 v,3 o,4 w1,5 w3,6 w2)
    cvt_kernel<<<(HID*HID/4+255)/256,256>>>(q_w, 0, (size_t)HID*HID);
    cvt_kernel<<<(KVDIM*HID/4+255)/256,256>>>(k_w, 1, (size_t)KVDIM*HID);
    cvt_kernel<<<(KVDIM*HID/4+255)/256,256>>>(v_w, 2, (size_t)KVDIM*HID);
    cvt_kernel<<<(HID*HID/4+255)/256,256>>>(o_w, 3, (size_t)HID*HID);
    cvt_kernel<<<(unsigned)((size_t)NEXP*FFD*HID/4/256),256>>>(w1, 4, (size_t)NEXP*FFD*HID);
    cvt_kernel<<<(unsigned)((size_t)NEXP*FFD*HID/4/256),256>>>(w3, 5, (size_t)NEXP*FFD*HID);
    cvt_kernel<<<(unsigned)((size_t)NEXP*HID*FFD/4/256),256>>>(w2, 6, (size_t)NEXP*HID*FFD);

    // attention block
    rmsnorm_kernel<<<SEQ,256>>>(hidden, ln1_w, 0);
    mma_gemm<<<dim3(HID/128,   SEQ/128, 1), 256>>>(0, 0, 0, (float*)0, (const float*)0, HID, HID,   0);
    mma_gemm<<<dim3(KVDIM/128, SEQ/128, 1), 256>>>(0, 1, 1, (float*)0, (const float*)0, HID, KVDIM, 0);
    mma_gemm<<<dim3(KVDIM/128, SEQ/128, 1), 256>>>(0, 2, 2, (float*)0, (const float*)0, HID, KVDIM, 0);
    rope_kernel<<<(SEQ*(HID/2))/256,  256>>>(0);
    rope_kernel<<<(SEQ*(KVDIM/2))/256,256>>>(1);
    flash_attn_kernel<<<dim3(SEQ/64, NHEAD),256>>>();
    mma_gemm<<<dim3(HID/128, SEQ/128, 1), 256>>>(1, 3, 3, (float*)0, hidden, HID, HID, 1);

    // MoE block (rmsnorm mode 1 reads g_h internally; first arg unused)
    rmsnorm_kernel<<<SEQ,256>>>((const float*)0, ln2_w, 1);
    route_kernel<<<SEQ,256>>>(gate_w);
    assign_kernel<<<1,256>>>();
    mma_gemm<<<dim3(FFD/128, SEQ/128, NEXP), 256>>>(2, 4, 4, (float*)0, (const float*)0, HID, FFD, 2);
    mma_gemm<<<dim3(FFD/128, SEQ/128, NEXP), 256>>>(2, 5, 5, (float*)0, (const float*)0, HID, FFD, 2);
    swiglu_kernel<<<(unsigned)((size_t)NASSIGN*FFD/4/256),256>>>();
    copy_h_kernel<<<(SEQ*HID)/256,256>>>(out);
    mma_gemm<<<dim3(HID/128, SEQ/128, NEXP), 256>>>(3, 6, -1, out, (const float*)0, FFD, HID, 3);
}

// round 9
// speedup vs baseline: 1.3547x; 1.0648x over previous
#include <cuda_runtime.h>
#include <cuda_bf16.h>
#include <cstdint>
#include <math.h>

#define SEQ   2048
#define HID   2048
#define HDIM  128
#define NHEAD 16
#define KVDIM 512
#define FFD   4096
#define NEXP  8
#define NASSIGN (2*SEQ)
#define PITCH 40
#define TB    (128*PITCH)
#define SMEM_DYN (2*4*TB*2)   // 2 stages x 4 arrays x 128x40 bf16 = 81920 B

typedef __nv_bfloat16 bf16;
typedef unsigned int u32;

// ---------------- scratch (device globals: allocation-free rule) ----------------
__device__ float g_q[SEQ*HID];
__device__ float g_k[SEQ*KVDIM];
__device__ float g_v[SEQ*KVDIM];
__device__ float g_h[SEQ*HID];
__device__ float g_x2[SEQ*HID];
__device__ float g_t1[NASSIGN*FFD];
__device__ float g_t3[NASSIGN*FFD];

__device__ bf16  g_xhi[SEQ*HID];
__device__ bf16  g_xlo[SEQ*HID];
__device__ bf16  g_x2hi[SEQ*HID];
__device__ bf16  g_x2lo[SEQ*HID];
__device__ bf16  g_ahi[SEQ*HID];
__device__ bf16  g_alo[SEQ*HID];
__device__ bf16  g_t1hi[NASSIGN*FFD];
__device__ bf16  g_t1lo[NASSIGN*FFD];

__device__ bf16  g_qwh[HID*HID];
__device__ bf16  g_qwl[HID*HID];
__device__ bf16  g_kwh[KVDIM*HID];
__device__ bf16  g_kwl[KVDIM*HID];
__device__ bf16  g_vwh[KVDIM*HID];
__device__ bf16  g_vwl[KVDIM*HID];
__device__ bf16  g_owh[HID*HID];
__device__ bf16  g_owl[HID*HID];
__device__ bf16  g_w1h[NEXP*FFD*HID];
__device__ bf16  g_w1l[NEXP*FFD*HID];
__device__ bf16  g_w3h[NEXP*FFD*HID];
__device__ bf16  g_w3l[NEXP*FFD*HID];
__device__ bf16  g_w2h[NEXP*HID*FFD];
__device__ bf16  g_w2l[NEXP*HID*FFD];

__device__ int   g_topi[SEQ*2];
__device__ float g_topv[SEQ*2];
__device__ int   g_tok[NASSIGN];
__device__ float g_wgt[NASSIGN];
__device__ int   g_cnt[NEXP];
__device__ int   g_off[NEXP];

// ---------------- helpers ----------------
__device__ __forceinline__ void split2(float v, bf16& h, bf16& l){
    h = __float2bfloat16(v);
    l = __float2bfloat16(v - __bfloat162float(h));
}

__device__ __forceinline__ void ldsm4(u32& r0, u32& r1, u32& r2, u32& r3, const bf16* p){
    u32 a = (u32)__cvta_generic_to_shared(p);
    asm volatile("ldmatrix.sync.aligned.m8n8.x4.shared.b16 {%0,%1,%2,%3}, [%4];"
        : "=r"(r0), "=r"(r1), "=r"(r2), "=r"(r3) : "r"(a));
}

__device__ __forceinline__ void mma_bf16(float* c, const u32* a, const u32* b){
    asm volatile("mma.sync.aligned.m16n8k16.row.col.f32.bf16.bf16.f32 "
        "{%0,%1,%2,%3}, {%4,%5,%6,%7}, {%8,%9}, {%0,%1,%2,%3};"
        : "+f"(c[0]), "+f"(c[1]), "+f"(c[2]), "+f"(c[3])
        : "r"(a[0]), "r"(a[1]), "r"(a[2]), "r"(a[3]), "r"(b[0]), "r"(b[1]));
}

__device__ __forceinline__ void cp16(u32 dst, const void* src){
    asm volatile("cp.async.cg.shared.global [%0], [%1], 16;" :: "r"(dst), "l"(src));
}

// weight-pair selector (device side)
__device__ __forceinline__ void sel_w(int s, const bf16*& hi, const bf16*& lo){
    switch (s){
        case 0: hi = g_qwh; lo = g_qwl; break;
        case 1: hi = g_kwh; lo = g_kwl; break;
        case 2: hi = g_vwh; lo = g_vwl; break;
        case 3: hi = g_owh; lo = g_owl; break;
        case 4: hi = g_w1h; lo = g_w1l; break;
        case 5: hi = g_w3h; lo = g_w3l; break;
        default: hi = g_w2h; lo = g_w2l; break;
    }
}

__device__ __forceinline__ void sel_a(int s, const bf16*& hi, const bf16*& lo){
    switch (s){
        case 0: hi = g_xhi;  lo = g_xlo;  break;
        case 1: hi = g_ahi;  lo = g_alo;  break;
        case 2: hi = g_x2hi; lo = g_x2lo; break;
        default: hi = g_t1hi; lo = g_t1lo; break;
    }
}

__device__ __forceinline__ float* sel_c(int s, float* ext){
    switch (s){
        case 0: return g_q;
        case 1: return g_k;
        case 2: return g_v;
        case 3: return g_h;
        case 4: return g_t1;
        case 5: return g_t3;
        default: return ext;
    }
}

// ---------------- fp32 -> bf16 hi/lo conversion (dst picked by selector) ----------------
__global__ void cvt_kernel(const float* __restrict__ src, int wsel, size_t n)
{
    const bf16 *hic, *loc;
    sel_w(wsel, hic, loc);
    bf16* hi = (bf16*)hic;
    bf16* lo = (bf16*)loc;
    size_t i = ((size_t)blockIdx.x*256 + threadIdx.x)*4;
    if (i >= n) return;
    float4 v = *(const float4*)(src + i);
    bf16 h0,l0,h1,l1,h2,l2,h3,l3;
    split2(v.x,h0,l0); split2(v.y,h1,l1); split2(v.z,h2,l2); split2(v.w,h3,l3);
    __nv_bfloat162 ph0; ph0.x=h0; ph0.y=h1;
    __nv_bfloat162 ph1; ph1.x=h2; ph1.y=h3;
    __nv_bfloat162 pl0; pl0.x=l0; pl0.y=l1;
    __nv_bfloat162 pl1; pl1.x=l2; pl1.y=l3;
    *(__nv_bfloat162*)(hi+i)   = ph0;
    *(__nv_bfloat162*)(hi+i+2) = ph1;
    *(__nv_bfloat162*)(lo+i)   = pl0;
    *(__nv_bfloat162*)(lo+i+2) = pl1;
}

// ---------------- rmsnorm ----------------
__global__ void rmsnorm_kernel(const float* __restrict__ in_ext, const float* __restrict__ w, int mode)
{
    const float* in = mode ? (const float*)g_h : in_ext;
    bf16* hi = mode ? g_x2hi : g_xhi;
    bf16* lo = mode ? g_x2lo : g_xlo;
    float* f32out = mode ? g_x2 : (float*)0;
    int row = blockIdx.x;
    const float* x = in + (size_t)row*HID;
    __shared__ float red[256];
    float ss = 0.f;
    for (int i = threadIdx.x; i < HID; i += 256) { float v = x[i]; ss += v*v; }
    red[threadIdx.x] = ss; __syncthreads();
    for (int s = 128; s > 0; s >>= 1) {
        if (threadIdx.x < s) red[threadIdx.x] += red[threadIdx.x+s];
        __syncthreads();
    }
    float rs = rsqrtf(red[0]/(float)HID + 1e-5f);
    size_t base = (size_t)row*HID;
    for (int i = threadIdx.x; i < HID; i += 256){
        float v = x[i]*rs*w[i];
        bf16 h,l; split2(v,h,l);
        hi[base+i]=h; lo[base+i]=l;
        if (f32out) f32out[base+i]=v;
    }
}

// ---------------- MMA GEMM: C = A * B^T (bf16x3 split, fp32 accum, cp.async 2-stage) --------
// mode 0: dense store | 1: dense + addend | 2: moe gather-in | 3: moe scatter-out
__global__ __launch_bounds__(256,1) void mma_gemm(
    int asel, int bsel, int csel, float* __restrict__ Cext,
    const float* __restrict__ addend, int K, int N, int mode)
{
    extern __shared__ __align__(16) bf16 dsm[];
    u32 sbase = (u32)__cvta_generic_to_shared(dsm);

    const bf16 *Ahi, *Alo, *Bhi, *Blo;
    sel_a(asel, Ahi, Alo);
    sel_w(bsel, Bhi, Blo);
    float* C = sel_c(csel, Cext);

    int tid = threadIdx.x, lane = tid & 31, wid = tid >> 5;
    int m0 = blockIdx.y*128, n0 = blockIdx.x*128;
    int cnt = 0, off = 0;
    if (mode >= 2){
        int z = blockIdx.z;
        cnt = g_cnt[z]; off = g_off[z];
        if (m0 >= cnt) return;
        Bhi += (size_t)z*N*K; Blo += (size_t)z*N*K;
    }

    int sr = tid >> 1, sh = (tid & 1)*16;
    int arow;
    if (mode == 2)      arow = g_tok[off + min(m0+sr, cnt-1)];
    else if (mode == 3) arow = off + min(m0+sr, cnt-1);
    else                arow = m0 + sr;
    const bf16* psrc[4];
    psrc[0] = Ahi + (size_t)arow*K + sh;
    psrc[1] = Alo + (size_t)arow*K + sh;
    psrc[2] = Bhi + (size_t)(n0+sr)*K + sh;
    psrc[3] = Blo + (size_t)(n0+sr)*K + sh;
    u32 soff = (u32)(sr*PITCH + sh)*2;   // byte offset within one array

    int wm = (wid & 1)*64, wn = (wid >> 1)*32;
    float acc[4][4][4];
    #pragma unroll
    for (int mi=0;mi<4;mi++)
        #pragma unroll
        for (int ni=0;ni<4;ni++)
            #pragma unroll
            for (int r=0;r<4;r++) acc[mi][ni][r]=0.f;

    int niter = K >> 5;

    // prologue: stage 0 loads for tile 0
    #pragma unroll
    for (int a4=0;a4<4;a4++){
        u32 d = sbase + (u32)(a4*TB*2) + soff;
        cp16(d, psrc[a4]);
        cp16(d+16, psrc[a4]+8);
    }
    asm volatile("cp.async.commit_group;");

    for (int it=0; it<niter; it++){
        if (it+1 < niter){
            int st = (it+1)&1;
            int k0 = (it+1)<<5;
            #pragma unroll
            for (int a4=0;a4<4;a4++){
                u32 d = sbase + (u32)((st*4+a4)*TB*2) + soff;
                cp16(d, psrc[a4]+k0);
                cp16(d+16, psrc[a4]+k0+8);
            }
        }
        asm volatile("cp.async.commit_group;");
        asm volatile("cp.async.wait_group 1;");
        __syncthreads();

        int cur = it&1;
        bf16* bAhi = dsm + (cur*4+0)*TB;
        bf16* bAlo = dsm + (cur*4+1)*TB;
        bf16* bBhi = dsm + (cur*4+2)*TB;
        bf16* bBlo = dsm + (cur*4+3)*TB;

        #pragma unroll
        for (int ks=0; ks<32; ks+=16){
            u32 fah[4][4], fal[4][4], fbh[4][2], fbl[4][2];
            int ar = lane & 15;
            int ac = ks + ((lane >> 4) << 3);
            #pragma unroll
            for (int mi=0;mi<4;mi++){
                ldsm4(fah[mi][0],fah[mi][1],fah[mi][2],fah[mi][3], &bAhi[(wm+mi*16+ar)*PITCH + ac]);
                ldsm4(fal[mi][0],fal[mi][1],fal[mi][2],fal[mi][3], &bAlo[(wm+mi*16+ar)*PITCH + ac]);
            }
            int br = ((lane >> 4) << 3) + (lane & 7);
            int bc = ks + (((lane >> 3) & 1) << 3);
            #pragma unroll
            for (int np=0;np<2;np++){
                ldsm4(fbh[np*2][0],fbh[np*2][1],fbh[np*2+1][0],fbh[np*2+1][1], &bBhi[(wn+np*16+br)*PITCH + bc]);
                ldsm4(fbl[np*2][0],fbl[np*2][1],fbl[np*2+1][0],fbl[np*2+1][1], &bBlo[(wn+np*16+br)*PITCH + bc]);
            }
            #pragma unroll
            for (int mi=0;mi<4;mi++)
                #pragma unroll
                for (int ni=0;ni<4;ni++){
                    mma_bf16(acc[mi][ni], fah[mi], fbh[ni]);
                    mma_bf16(acc[mi][ni], fah[mi], fbl[ni]);
                    mma_bf16(acc[mi][ni], fal[mi], fbh[ni]);
                }
        }
        __syncthreads();
    }

    int tr = lane >> 2, tc = (lane & 3)*2;
    if (mode <= 1){
        #pragma unroll
        for (int mi=0;mi<4;mi++)
            #pragma unroll
            for (int hh=0;hh<2;hh++){
                int row = m0 + wm + mi*16 + tr + hh*8;
                float* cp = C + (size_t)row*N + n0 + wn;
                #pragma unroll
                for (int ni=0;ni<4;ni++){
                    float v0 = acc[mi][ni][hh*2], v1 = acc[mi][ni][hh*2+1];
                    if (mode==1){
                        const float* ap = addend + (size_t)row*N + n0 + wn;
                        v0 += ap[ni*8+tc]; v1 += ap[ni*8+tc+1];
                    }
                    cp[ni*8+tc] = v0; cp[ni*8+tc+1] = v1;
                }
            }
    } else if (mode == 2){
        #pragma unroll
        for (int mi=0;mi<4;mi++)
            #pragma unroll
            for (int hh=0;hh<2;hh++){
                int slot = m0 + wm + mi*16 + tr + hh*8;
                if (slot < cnt){
                    float* cp = C + (size_t)(off+slot)*N + n0 + wn;
                    #pragma unroll
                    for (int ni=0;ni<4;ni++){
                        cp[ni*8+tc]   = acc[mi][ni][hh*2];
                        cp[ni*8+tc+1] = acc[mi][ni][hh*2+1];
                    }
                }
            }
    } else {
        #pragma unroll
        for (int mi=0;mi<4;mi++)
            #pragma unroll
            for (int hh=0;hh<2;hh++){
                int slot = m0 + wm + mi*16 + tr + hh*8;
                if (slot < cnt){
                    int tok = g_tok[off+slot];
                    float w = g_wgt[off+slot];
                    float* op = C + (size_t)tok*HID + n0 + wn;
                    #pragma unroll
                    for (int ni=0;ni<4;ni++){
                        atomicAdd(&op[ni*8+tc],   w*acc[mi][ni][hh*2]);
                        atomicAdd(&op[ni*8+tc+1], w*acc[mi][ni][hh*2+1]);
                    }
                }
            }
    }
}

// ---------------- RoPE (in-place on g_q / g_k) ----------------
__global__ void rope_kernel(int isK)
{
    int ncols = isK ? KVDIM : HID;
    int half  = ncols >> 1;
    int idx = blockIdx.x*256 + threadIdx.x;
    if (idx >= SEQ*half) return;
    int t = idx / half;
    int p = idx - t*half;
    int head = p >> 6;
    int d = p & 63;
    float* buf = isK ? g_k : g_q;
    int c1 = head*HDIM + d;
    float inv = expf(-(float)d * (9.210340371976184f/64.f));
    float ang = (float)t * inv;
    float cs = cosf(ang), sn = sinf(ang);
    float* b1 = buf + (size_t)t*ncols + c1;
    float x1 = b1[0], x2 = b1[64];
    b1[0]  = x1*cs - x2*sn;
    b1[64] = x2*cs + x1*sn;
}

// ---------------- flash attention (causal, GQA 4:1), writes bf16 hi/lo ----------------
__global__ __launch_bounds__(256,1) void flash_attn_kernel()
{
    __shared__ float KV[64][128];
    int qt = blockIdx.x, h = blockIdx.y;
    int kvh = h >> 2;
    int tid = threadIdx.x;
    int row = tid >> 2;
    int quar = tid & 3;
    int qrow = qt*64 + row;
    const float scale = 0.08838834764831845f;
    float qreg[32];
    const float4* qp = (const float4*)&g_q[(size_t)qrow*HID + h*HDIM + quar*32];
    #pragma unroll
    for (int i=0;i<8;i++){
        float4 v = qp[i];
        qreg[4*i+0]=v.x*scale; qreg[4*i+1]=v.y*scale;
        qreg[4*i+2]=v.z*scale; qreg[4*i+3]=v.w*scale;
    }
    float m = -1e30f, l = 0.f;
    float o[32];
    #pragma unroll
    for (int i=0;i<32;i++) o[i]=0.f;

    for (int kt = 0; kt <= qt; kt++){
        int k0 = kt*64;
        __syncthreads();
        {
            const float4* src = (const float4*)&g_k[(size_t)(k0+row)*KVDIM + kvh*HDIM + quar*32];
            float4* dst = (float4*)&KV[row][quar*32];
            #pragma unroll
            for (int i=0;i<8;i++) dst[i]=src[i];
        }
        __syncthreads();
        float s[64];
        #pragma unroll
        for (int j=0;j<64;j++){
            const float4* kp = (const float4*)&KV[j][quar*32];
            float acc = 0.f;
            #pragma unroll
            for (int i=0;i<8;i++){
                float4 kv = kp[i];
                acc += qreg[4*i+0]*kv.x + qreg[4*i+1]*kv.y
                     + qreg[4*i+2]*kv.z + qreg[4*i+3]*kv.w;
            }
            acc += __shfl_xor_sync(0xffffffffu, acc, 1);
            acc += __shfl_xor_sync(0xffffffffu, acc, 2);
            s[j] = acc;
        }
        if (kt == qt){
            #pragma unroll
            for (int j=0;j<64;j++) if (k0+j > qrow) s[j] = -1e30f;
        }
        float nm = m;
        #pragma unroll
        for (int j=0;j<64;j++) nm = fmaxf(nm, s[j]);
        float corr = __expf(m - nm);
        float ls = 0.f;
        #pragma unroll
        for (int j=0;j<64;j++){ s[j] = __expf(s[j]-nm); ls += s[j]; }
        l = l*corr + ls;
        #pragma unroll
        for (int i=0;i<32;i++) o[i] *= corr;
        m = nm;
        __syncthreads();
        {
            const float4* src = (const float4*)&g_v[(size_t)(k0+row)*KVDIM + kvh*HDIM + quar*32];
            float4* dst = (float4*)&KV[row][quar*32];
            #pragma unroll
            for (int i=0;i<8;i++) dst[i]=src[i];
        }
        __syncthreads();
        #pragma unroll
        for (int j=0;j<64;j++){
            float p = s[j];
            const float4* vp = (const float4*)&KV[j][quar*32];
            #pragma unroll
            for (int i=0;i<8;i++){
                float4 vv = vp[i];
                o[4*i+0]+=p*vv.x; o[4*i+1]+=p*vv.y;
                o[4*i+2]+=p*vv.z; o[4*i+3]+=p*vv.w;
            }
        }
    }
    float invl = 1.f/l;
    size_t base = (size_t)qrow*HID + h*HDIM + quar*32;
    #pragma unroll
    for (int i=0;i<32;i+=2){
        float v0 = o[i]*invl, v1 = o[i+1]*invl;
        bf16 h0,l0,h1,l1;
        split2(v0,h0,l0); split2(v1,h1,l1);
        __nv_bfloat162 ph; ph.x=h0; ph.y=h1;
        __nv_bfloat162 pl; pl.x=l0; pl.y=l1;
        *(__nv_bfloat162*)(g_ahi+base+i) = ph;
        *(__nv_bfloat162*)(g_alo+base+i) = pl;
    }
}

// ---------------- routing ----------------
__global__ void route_kernel(const float* __restrict__ gate_w)
{
    int t = blockIdx.x;
    int wid = threadIdx.x >> 5, lane = threadIdx.x & 31;
    __shared__ float slog[NEXP];
    const float* x  = g_x2 + (size_t)t*HID;
    const float* gw = gate_w + (size_t)wid*HID;
    float acc = 0.f;
    for (int i = lane; i < HID; i += 32) acc += x[i]*gw[i];
    #pragma unroll
    for (int o=16;o;o>>=1) acc += __shfl_xor_sync(0xffffffffu, acc, o);
    if (lane == 0) slog[wid] = acc;
    __syncthreads();
    if (threadIdx.x == 0){
        float mx = slog[0];
        for (int e=1;e<NEXP;e++) mx = fmaxf(mx, slog[e]);
        float p[NEXP]; float se = 0.f;
        for (int e=0;e<NEXP;e++){ p[e] = expf(slog[e]-mx); se += p[e]; }
        float inv = 1.f/se;
        for (int e=0;e<NEXP;e++) p[e] *= inv;
        int i1 = 0;
        for (int e=1;e<NEXP;e++) if (p[e] > p[i1]) i1 = e;
        int i2 = (i1==0) ? 1 : 0;
        for (int e=0;e<NEXP;e++) if (e!=i1 && p[e] > p[i2]) i2 = e;
        float v1 = p[i1], v2 = p[i2], s2 = 1.f/(v1+v2);
        g_topi[2*t]=i1; g_topi[2*t+1]=i2;
        g_topv[2*t]=v1*s2; g_topv[2*t+1]=v2*s2;
    }
}

// ---------------- deterministic per-expert token lists ----------------
__global__ void assign_kernel()
{
    __shared__ int scn[256];
    int tid = threadIdx.x;
    int base = 0;
    for (int e=0;e<NEXP;e++){
        int fl[8]; float fw[8];
        int local = 0;
        #pragma unroll
        for (int j=0;j<8;j++){
            int t = tid*8 + j;
            int a = g_topi[2*t], b = g_topi[2*t+1];
            float w = 0.f; int f = 0;
            if (a==e){ w += g_topv[2*t];   f = 1; }
            if (b==e){ w += g_topv[2*t+1]; f = 1; }
            fl[j]=f; fw[j]=w; local += f;
        }
        scn[tid]=local;
        __syncthreads();
        for (int d=1; d<256; d<<=1){
            int v = (tid>=d) ? scn[tid-d] : 0;
            __syncthreads();
            scn[tid] += v;
            __syncthreads();
        }
        int pos   = base + scn[tid] - local;
        int total = scn[255];
        #pragma unroll
        for (int j=0;j<8;j++){
            if (fl[j]){ g_tok[pos]=tid*8+j; g_wgt[pos]=fw[j]; pos++; }
        }
        if (tid==0){ g_cnt[e]=total; g_off[e]=base; }
        base += total;
        __syncthreads();
    }
}

// ---------------- swiglu: t1 = silu(t1)*t3, write bf16 hi/lo ----------------
__global__ void swiglu_kernel()
{
    size_t i = ((size_t)blockIdx.x*256 + threadIdx.x)*4;
    float4 a = *(const float4*)(g_t1+i);
    float4 b = *(const float4*)(g_t3+i);
    float v0 = a.x*b.x/(1.f+__expf(-a.x));
    float v1 = a.y*b.y/(1.f+__expf(-a.y));
    float v2 = a.z*b.z/(1.f+__expf(-a.z));
    float v3 = a.w*b.w/(1.f+__expf(-a.w));
    bf16 h0,l0,h1,l1,h2,l2,h3,l3;
    split2(v0,h0,l0); split2(v1,h1,l1); split2(v2,h2,l2); split2(v3,h3,l3);
    __nv_bfloat162 ph0; ph0.x=h0; ph0.y=h1;
    __nv_bfloat162 ph1; ph1.x=h2; ph1.y=h3;
    __nv_bfloat162 pl0; pl0.x=l0; pl0.y=l1;
    __nv_bfloat162 pl1; pl1.x=l2; pl1.y=l3;
    *(__nv_bfloat162*)(g_t1hi+i)   = ph0;
    *(__nv_bfloat162*)(g_t1hi+i+2) = ph1;
    *(__nv_bfloat162*)(g_t1lo+i)   = pl0;
    *(__nv_bfloat162*)(g_t1lo+i+2) = pl1;
}

// ---------------- base: out = h ----------------
__global__ void copy_h_kernel(float* __restrict__ out)
{
    int i = blockIdx.x*256 + threadIdx.x;
    out[i] = g_h[i];
}

// ---------------- launch ----------------
extern "C" void kernel_launch(void* const* d_in, const int* in_sizes, int n_in,
                              void* d_out, int out_size)
{
    (void)in_sizes; (void)n_in; (void)out_size;
    const float* hidden = (const float*)d_in[0];
    const float* ln1_w  = (const float*)d_in[1];
    const float* ln2_w  = (const float*)d_in[2];
    const float* q_w    = (const float*)d_in[3];
    const float* k_w    = (const float*)d_in[4];
    const float* v_w    = (const float*)d_in[5];
    const float* o_w    = (const float*)d_in[6];
    const float* gate_w = (const float*)d_in[7];
    const float* w1     = (const float*)d_in[8];
    const float* w3     = (const float*)d_in[9];
    const float* w2     = (const float*)d_in[10];
    float* out = (float*)d_out;

    cudaFuncSetAttribute(mma_gemm, cudaFuncAttributeMaxDynamicSharedMemorySize, SMEM_DYN);

    // weight conversion fp32 -> bf16 hi/lo (selectors: 0 q,1 k,2 v,3 o,4 w1,5 w3,6 w2)
    cvt_kernel<<<(HID*HID/4+255)/256,256>>>(q_w, 0, (size_t)HID*HID);
    cvt_kernel<<<(KVDIM*HID/4+255)/256,256>>>(k_w, 1, (size_t)KVDIM*HID);
    cvt_kernel<<<(KVDIM*HID/4+255)/256,256>>>(v_w, 2, (size_t)KVDIM*HID);
    cvt_kernel<<<(HID*HID/4+255)/256,256>>>(o_w, 3, (size_t)HID*HID);
    cvt_kernel<<<(unsigned)((size_t)NEXP*FFD*HID/4/256),256>>>(w1, 4, (size_t)NEXP*FFD*HID);
    cvt_kernel<<<(unsigned)((size_t)NEXP*FFD*HID/4/256),256>>>(w3, 5, (size_t)NEXP*FFD*HID);
    cvt_kernel<<<(unsigned)((size_t)NEXP*HID*FFD/4/256),256>>>(w2, 6, (size_t)NEXP*HID*FFD);

    // attention block
    rmsnorm_kernel<<<SEQ,256>>>(hidden, ln1_w, 0);
    mma_gemm<<<dim3(HID/128,   SEQ/128, 1), 256, SMEM_DYN>>>(0, 0, 0, (float*)0, (const float*)0, HID, HID,   0);
    mma_gemm<<<dim3(KVDIM/128, SEQ/128, 1), 256, SMEM_DYN>>>(0, 1, 1, (float*)0, (const float*)0, HID, KVDIM, 0);
    mma_gemm<<<dim3(KVDIM/128, SEQ/128, 1), 256, SMEM_DYN>>>(0, 2, 2, (float*)0, (const float*)0, HID, KVDIM, 0);
    rope_kernel<<<(SEQ*(HID/2))/256,  256>>>(0);
    rope_kernel<<<(SEQ*(KVDIM/2))/256,256>>>(1);
    flash_attn_kernel<<<dim3(SEQ/64, NHEAD),256>>>();
    mma_gemm<<<dim3(HID/128, SEQ/128, 1), 256, SMEM_DYN>>>(1, 3, 3, (float*)0, hidden, HID, HID, 1);

    // MoE block (rmsnorm mode 1 reads g_h internally; first arg unused)
    rmsnorm_kernel<<<SEQ,256>>>((const float*)0, ln2_w, 1);
    route_kernel<<<SEQ,256>>>(gate_w);
    assign_kernel<<<1,256>>>();
    mma_gemm<<<dim3(FFD/128, SEQ/128, NEXP), 256, SMEM_DYN>>>(2, 4, 4, (float*)0, (const float*)0, HID, FFD, 2);
    mma_gemm<<<dim3(FFD/128, SEQ/128, NEXP), 256, SMEM_DYN>>>(2, 5, 5, (float*)0, (const float*)0, HID, FFD, 2);
    swiglu_kernel<<<(unsigned)((size_t)NASSIGN*FFD/4/256),256>>>();
    copy_h_kernel<<<(SEQ*HID)/256,256>>>(out);
    mma_gemm<<<dim3(HID/128, SEQ/128, NEXP), 256, SMEM_DYN>>>(3, 6, -1, out, (const float*)0, FFD, HID, 3);
}

// round 11
// speedup vs baseline: 1.6004x; 1.1814x over previous
#include <cuda_runtime.h>
#include <cuda_bf16.h>
#include <cuda_fp16.h>
#include <cstdint>
#include <math.h>

#define SEQ   2048
#define HID   2048
#define HDIM  128
#define NHEAD 16
#define KVDIM 512
#define FFD   4096
#define NEXP  8
#define NASSIGN (2*SEQ)
#define PITCH 40
#define TB    (128*PITCH)            // halves per operand tile
#define SMEM_DYN (2*3*TB*2)          // 2 stages x 3 arrays x 128x40 fp16 = 61440 B

typedef __half fp16;
typedef unsigned int u32;

// ---------------- scratch (device globals: allocation-free rule) ----------------
__device__ float g_q[SEQ*HID];
__device__ float g_k[SEQ*KVDIM];
__device__ float g_v[SEQ*KVDIM];
__device__ float g_h[SEQ*HID];
__device__ float g_t1[NASSIGN*FFD];
__device__ float g_t3[NASSIGN*FFD];

__device__ fp16  g_xhi[SEQ*HID];
__device__ fp16  g_xlo[SEQ*HID];
__device__ fp16  g_x2hi[SEQ*HID];
__device__ fp16  g_x2lo[SEQ*HID];
__device__ fp16  g_ahi[SEQ*HID];
__device__ fp16  g_alo[SEQ*HID];
__device__ fp16  g_t1hi[NASSIGN*FFD];
__device__ fp16  g_t1lo[NASSIGN*FFD];

__device__ fp16  g_qw[HID*HID];
__device__ fp16  g_kw[KVDIM*HID];
__device__ fp16  g_vw[KVDIM*HID];
__device__ fp16  g_ow[HID*HID];
__device__ fp16  g_w1[NEXP*FFD*HID];
__device__ fp16  g_w3[NEXP*FFD*HID];
__device__ fp16  g_w2[NEXP*HID*FFD];

__device__ int   g_topi[SEQ*2];
__device__ float g_topv[SEQ*2];
__device__ int   g_tok[NASSIGN];
__device__ float g_wgt[NASSIGN];
__device__ int   g_cnt[NEXP];
__device__ int   g_off[NEXP];

// ---------------- helpers ----------------
__device__ __forceinline__ void split2h(float v, fp16& h, fp16& l){
    h = __float2half(v);
    l = __float2half(v - __half2float(h));
}

__device__ __forceinline__ void ldsm4(u32& r0, u32& r1, u32& r2, u32& r3, const fp16* p){
    u32 a = (u32)__cvta_generic_to_shared(p);
    asm volatile("ldmatrix.sync.aligned.m8n8.x4.shared.b16 {%0,%1,%2,%3}, [%4];"
        : "=r"(r0), "=r"(r1), "=r"(r2), "=r"(r3) : "r"(a));
}

__device__ __forceinline__ void mma_f16(float* c, const u32* a, const u32* b){
    asm volatile("mma.sync.aligned.m16n8k16.row.col.f32.f16.f16.f32 "
        "{%0,%1,%2,%3}, {%4,%5,%6,%7}, {%8,%9}, {%0,%1,%2,%3};"
        : "+f"(c[0]), "+f"(c[1]), "+f"(c[2]), "+f"(c[3])
        : "r"(a[0]), "r"(a[1]), "r"(a[2]), "r"(a[3]), "r"(b[0]), "r"(b[1]));
}

__device__ __forceinline__ void cp16(u32 dst, const void* src){
    asm volatile("cp.async.cg.shared.global [%0], [%1], 16;" :: "r"(dst), "l"(src));
}

// weight selector (device side)
__device__ __forceinline__ const fp16* sel_w(int s){
    switch (s){
        case 0: return g_qw;
        case 1: return g_kw;
        case 2: return g_vw;
        case 3: return g_ow;
        case 4: return g_w1;
        case 5: return g_w3;
        default: return g_w2;
    }
}

__device__ __forceinline__ void sel_a(int s, const fp16*& hi, const fp16*& lo){
    switch (s){
        case 0: hi = g_xhi;  lo = g_xlo;  break;
        case 1: hi = g_ahi;  lo = g_alo;  break;
        case 2: hi = g_x2hi; lo = g_x2lo; break;
        default: hi = g_t1hi; lo = g_t1lo; break;
    }
}

__device__ __forceinline__ float* sel_c(int s, float* ext){
    switch (s){
        case 0: return g_q;
        case 1: return g_k;
        case 2: return g_v;
        case 3: return g_h;
        case 4: return g_t1;
        case 5: return g_t3;
        default: return ext;
    }
}

// ---------------- fp32 -> fp16 conversion (8 elems/thread, 16B stores) ----------------
__global__ void cvt_kernel(const float* __restrict__ src, int wsel, size_t n)
{
    fp16* dst = (fp16*)sel_w(wsel);
    size_t i = ((size_t)blockIdx.x*256 + threadIdx.x)*8;
    if (i >= n) return;
    float4 a = *(const float4*)(src + i);
    float4 b = *(const float4*)(src + i + 4);
    __half2 h0 = __floats2half2_rn(a.x, a.y);
    __half2 h1 = __floats2half2_rn(a.z, a.w);
    __half2 h2 = __floats2half2_rn(b.x, b.y);
    __half2 h3 = __floats2half2_rn(b.z, b.w);
    *(uint4*)(dst + i) = make_uint4(*(u32*)&h0, *(u32*)&h1, *(u32*)&h2, *(u32*)&h3);
}

// ---------------- rmsnorm: mode 0 -> g_xhi/lo ; mode 1 -> g_x2hi/lo (reads g_h) --------
__global__ void rmsnorm_kernel(const float* __restrict__ in_ext, const float* __restrict__ w, int mode)
{
    const float* in = mode ? (const float*)g_h : in_ext;
    fp16* hi = mode ? g_x2hi : g_xhi;
    fp16* lo = mode ? g_x2lo : g_xlo;
    int row = blockIdx.x;
    const float* x = in + (size_t)row*HID;
    __shared__ float red[256];
    float ss = 0.f;
    for (int i = threadIdx.x; i < HID; i += 256) { float v = x[i]; ss += v*v; }
    red[threadIdx.x] = ss; __syncthreads();
    for (int s = 128; s > 0; s >>= 1) {
        if (threadIdx.x < s) red[threadIdx.x] += red[threadIdx.x+s];
        __syncthreads();
    }
    float rs = rsqrtf(red[0]/(float)HID + 1e-5f);
    size_t base = (size_t)row*HID;
    for (int i = threadIdx.x; i < HID; i += 256){
        float v = x[i]*rs*w[i];
        fp16 h,l; split2h(v,h,l);
        hi[base+i]=h; lo[base+i]=l;
    }
}

// ---------------- MMA GEMM: C = A * B^T (fp16x2: Ahi·B + Alo·B, fp32 accum) ----------------
// mode 0: dense (z picks (bsel,csel) or (b2,c2)) | 1: dense + addend
// mode 2: moe gather-in (z&7 = expert, z>=8 -> w3/t3) | 3: moe scatter-out (z = expert)
__global__ __launch_bounds__(256,2) void mma_gemm(
    int asel, int bsel, int csel, int b2, int c2,
    float* __restrict__ Cext, const float* __restrict__ addend,
    int K, int N, int mode)
{
    extern __shared__ __align__(16) fp16 dsm[];
    u32 sbase = (u32)__cvta_generic_to_shared(dsm);

    int z = blockIdx.z;
    if (mode <= 1 && z == 1){ bsel = b2; csel = c2; }
    int expt = 0;
    if (mode == 2){ expt = z & 7; bsel = (z >= 8) ? 5 : 4; csel = bsel; }
    if (mode == 3) expt = z;

    const fp16 *Ahi, *Alo;
    sel_a(asel, Ahi, Alo);
    const fp16* B = sel_w(bsel);
    float* C = sel_c(csel, Cext);

    int tid = threadIdx.x, lane = tid & 31, wid = tid >> 5;
    int m0 = blockIdx.y*128, n0 = blockIdx.x*128;
    int cnt = 0, off = 0;
    if (mode >= 2){
        cnt = g_cnt[expt]; off = g_off[expt];
        if (m0 >= cnt) return;
        B += (size_t)expt*N*K;
    }

    int sr = tid >> 1, sh = (tid & 1)*16;
    int arow;
    if (mode == 2)      arow = g_tok[off + min(m0+sr, cnt-1)];
    else if (mode == 3) arow = off + min(m0+sr, cnt-1);
    else                arow = m0 + sr;
    const fp16* psrc[3];
    psrc[0] = Ahi + (size_t)arow*K + sh;
    psrc[1] = Alo + (size_t)arow*K + sh;
    psrc[2] = B   + (size_t)(n0+sr)*K + sh;
    u32 soff = (u32)(sr*PITCH + sh)*2;

    float acc[4][4][4];
    #pragma unroll
    for (int mi=0;mi<4;mi++)
        #pragma unroll
        for (int ni=0;ni<4;ni++)
            #pragma unroll
            for (int r=0;r<4;r++) acc[mi][ni][r]=0.f;

    int wm = (wid & 1)*64, wn = (wid >> 1)*32;
    int niter = K >> 5;

    #pragma unroll
    for (int a3=0;a3<3;a3++){
        u32 d = sbase + (u32)(a3*TB*2) + soff;
        cp16(d, psrc[a3]);
        cp16(d+16, psrc[a3]+8);
    }
    asm volatile("cp.async.commit_group;");

    for (int it=0; it<niter; it++){
        if (it+1 < niter){
            int st = (it+1)&1;
            int k0 = (it+1)<<5;
            #pragma unroll
            for (int a3=0;a3<3;a3++){
                u32 d = sbase + (u32)((st*3+a3)*TB*2) + soff;
                cp16(d, psrc[a3]+k0);
                cp16(d+16, psrc[a3]+k0+8);
            }
        }
        asm volatile("cp.async.commit_group;");
        asm volatile("cp.async.wait_group 1;");
        __syncthreads();

        int cur = it&1;
        fp16* bAhi = dsm + (cur*3+0)*TB;
        fp16* bAlo = dsm + (cur*3+1)*TB;
        fp16* bB   = dsm + (cur*3+2)*TB;

        #pragma unroll
        for (int ks=0; ks<32; ks+=16){
            u32 fah[4][4], fal[4][4], fb[4][2];
            int ar = lane & 15;
            int ac = ks + ((lane >> 4) << 3);
            #pragma unroll
            for (int mi=0;mi<4;mi++){
                ldsm4(fah[mi][0],fah[mi][1],fah[mi][2],fah[mi][3], &bAhi[(wm+mi*16+ar)*PITCH + ac]);
                ldsm4(fal[mi][0],fal[mi][1],fal[mi][2],fal[mi][3], &bAlo[(wm+mi*16+ar)*PITCH + ac]);
            }
            int br = ((lane >> 4) << 3) + (lane & 7);
            int bc = ks + (((lane >> 3) & 1) << 3);
            #pragma unroll
            for (int np=0;np<2;np++){
                ldsm4(fb[np*2][0],fb[np*2][1],fb[np*2+1][0],fb[np*2+1][1], &bB[(wn+np*16+br)*PITCH + bc]);
            }
            #pragma unroll
            for (int mi=0;mi<4;mi++)
                #pragma unroll
                for (int ni=0;ni<4;ni++){
                    mma_f16(acc[mi][ni], fah[mi], fb[ni]);
                    mma_f16(acc[mi][ni], fal[mi], fb[ni]);
                }
        }
        __syncthreads();
    }

    int tr = lane >> 2, tc = (lane & 3)*2;
    if (mode <= 1){
        #pragma unroll
        for (int mi=0;mi<4;mi++)
            #pragma unroll
            for (int hh=0;hh<2;hh++){
                int row = m0 + wm + mi*16 + tr + hh*8;
                float* cp = C + (size_t)row*N + n0 + wn;
                #pragma unroll
                for (int ni=0;ni<4;ni++){
                    float v0 = acc[mi][ni][hh*2], v1 = acc[mi][ni][hh*2+1];
                    if (mode==1){
                        const float* ap = addend + (size_t)row*N + n0 + wn;
                        v0 += ap[ni*8+tc]; v1 += ap[ni*8+tc+1];
                    }
                    cp[ni*8+tc] = v0; cp[ni*8+tc+1] = v1;
                }
            }
    } else if (mode == 2){
        #pragma unroll
        for (int mi=0;mi<4;mi++)
            #pragma unroll
            for (int hh=0;hh<2;hh++){
                int slot = m0 + wm + mi*16 + tr + hh*8;
                if (slot < cnt){
                    float* cp = C + (size_t)(off+slot)*N + n0 + wn;
                    #pragma unroll
                    for (int ni=0;ni<4;ni++){
                        cp[ni*8+tc]   = acc[mi][ni][hh*2];
                        cp[ni*8+tc+1] = acc[mi][ni][hh*2+1];
                    }
                }
            }
    } else {
        #pragma unroll
        for (int mi=0;mi<4;mi++)
            #pragma unroll
            for (int hh=0;hh<2;hh++){
                int slot = m0 + wm + mi*16 + tr + hh*8;
                if (slot < cnt){
                    int tok = g_tok[off+slot];
                    float w = g_wgt[off+slot];
                    float* op = C + (size_t)tok*HID + n0 + wn;
                    #pragma unroll
                    for (int ni=0;ni<4;ni++){
                        atomicAdd(&op[ni*8+tc],   w*acc[mi][ni][hh*2]);
                        atomicAdd(&op[ni*8+tc+1], w*acc[mi][ni][hh*2+1]);
                    }
                }
            }
    }
}

// ---------------- RoPE (in-place on g_q / g_k) ----------------
__global__ void rope_kernel(int isK)
{
    int ncols = isK ? KVDIM : HID;
    int half  = ncols >> 1;
    int idx = blockIdx.x*256 + threadIdx.x;
    if (idx >= SEQ*half) return;
    int t = idx / half;
    int p = idx - t*half;
    int head = p >> 6;
    int d = p & 63;
    float* buf = isK ? g_k : g_q;
    int c1 = head*HDIM + d;
    float inv = expf(-(float)d * (9.210340371976184f/64.f));
    float ang = (float)t * inv;
    float cs = cosf(ang), sn = sinf(ang);
    float* b1 = buf + (size_t)t*ncols + c1;
    float x1 = b1[0], x2 = b1[64];
    b1[0]  = x1*cs - x2*sn;
    b1[64] = x2*cs + x1*sn;
}

// ---------------- flash attention (causal, GQA 4:1), writes fp16 hi/lo ----------------
__global__ __launch_bounds__(256,1) void flash_attn_kernel()
{
    __shared__ float KV[64][128];
    int qt = blockIdx.x, h = blockIdx.y;
    int kvh = h >> 2;
    int tid = threadIdx.x;
    int row = tid >> 2;
    int quar = tid & 3;
    int qrow = qt*64 + row;
    const float scale = 0.08838834764831845f;
    float qreg[32];
    const float4* qp = (const float4*)&g_q[(size_t)qrow*HID + h*HDIM + quar*32];
    #pragma unroll
    for (int i=0;i<8;i++){
        float4 v = qp[i];
        qreg[4*i+0]=v.x*scale; qreg[4*i+1]=v.y*scale;
        qreg[4*i+2]=v.z*scale; qreg[4*i+3]=v.w*scale;
    }
    float m = -1e30f, l = 0.f;
    float o[32];
    #pragma unroll
    for (int i=0;i<32;i++) o[i]=0.f;

    for (int kt = 0; kt <= qt; kt++){
        int k0 = kt*64;
        __syncthreads();
        {
            const float4* src = (const float4*)&g_k[(size_t)(k0+row)*KVDIM + kvh*HDIM + quar*32];
            float4* dst = (float4*)&KV[row][quar*32];
            #pragma unroll
            for (int i=0;i<8;i++) dst[i]=src[i];
        }
        __syncthreads();
        float s[64];
        #pragma unroll
        for (int j=0;j<64;j++){
            const float4* kp = (const float4*)&KV[j][quar*32];
            float acc = 0.f;
            #pragma unroll
            for (int i=0;i<8;i++){
                float4 kv = kp[i];
                acc += qreg[4*i+0]*kv.x + qreg[4*i+1]*kv.y
                     + qreg[4*i+2]*kv.z + qreg[4*i+3]*kv.w;
            }
            acc += __shfl_xor_sync(0xffffffffu, acc, 1);
            acc += __shfl_xor_sync(0xffffffffu, acc, 2);
            s[j] = acc;
        }
        if (kt == qt){
            #pragma unroll
            for (int j=0;j<64;j++) if (k0+j > qrow) s[j] = -1e30f;
        }
        float nm = m;
        #pragma unroll
        for (int j=0;j<64;j++) nm = fmaxf(nm, s[j]);
        float corr = __expf(m - nm);
        float ls = 0.f;
        #pragma unroll
        for (int j=0;j<64;j++){ s[j] = __expf(s[j]-nm); ls += s[j]; }
        l = l*corr + ls;
        #pragma unroll
        for (int i=0;i<32;i++) o[i] *= corr;
        m = nm;
        __syncthreads();
        {
            const float4* src = (const float4*)&g_v[(size_t)(k0+row)*KVDIM + kvh*HDIM + quar*32];
            float4* dst = (float4*)&KV[row][quar*32];
            #pragma unroll
            for (int i=0;i<8;i++) dst[i]=src[i];
        }
        __syncthreads();
        #pragma unroll
        for (int j=0;j<64;j++){
            float p = s[j];
            const float4* vp = (const float4*)&KV[j][quar*32];
            #pragma unroll
            for (int i=0;i<8;i++){
                float4 vv = vp[i];
                o[4*i+0]+=p*vv.x; o[4*i+1]+=p*vv.y;
                o[4*i+2]+=p*vv.z; o[4*i+3]+=p*vv.w;
            }
        }
    }
    float invl = 1.f/l;
    size_t base = (size_t)qrow*HID + h*HDIM + quar*32;
    #pragma unroll
    for (int i=0;i<32;i+=2){
        float v0 = o[i]*invl, v1 = o[i+1]*invl;
        fp16 h0,l0,h1,l1;
        split2h(v0,h0,l0); split2h(v1,h1,l1);
        __half2 ph; ph.x=h0; ph.y=h1;
        __half2 pl; pl.x=l0; pl.y=l1;
        *(__half2*)(g_ahi+base+i) = ph;
        *(__half2*)(g_alo+base+i) = pl;
    }
}

// ---------------- routing (reconstruct x2 = hi+lo, exact to ~1e-7) ----------------
__global__ void route_kernel(const float* __restrict__ gate_w)
{
    int t = blockIdx.x;
    int wid = threadIdx.x >> 5, lane = threadIdx.x & 31;
    __shared__ float slog[NEXP];
    const fp16* xh = g_x2hi + (size_t)t*HID;
    const fp16* xl = g_x2lo + (size_t)t*HID;
    const float* gw = gate_w + (size_t)wid*HID;
    float acc = 0.f;
    for (int i = lane; i < HID; i += 32)
        acc += (__half2float(xh[i]) + __half2float(xl[i]))*gw[i];
    #pragma unroll
    for (int o=16;o;o>>=1) acc += __shfl_xor_sync(0xffffffffu, acc, o);
    if (lane == 0) slog[wid] = acc;
    __syncthreads();
    if (threadIdx.x == 0){
        float mx = slog[0];
        for (int e=1;e<NEXP;e++) mx = fmaxf(mx, slog[e]);
        float p[NEXP]; float se = 0.f;
        for (int e=0;e<NEXP;e++){ p[e] = expf(slog[e]-mx); se += p[e]; }
        float inv = 1.f/se;
        for (int e=0;e<NEXP;e++) p[e] *= inv;
        int i1 = 0;
        for (int e=1;e<NEXP;e++) if (p[e] > p[i1]) i1 = e;
        int i2 = (i1==0) ? 1 : 0;
        for (int e=0;e<NEXP;e++) if (e!=i1 && p[e] > p[i2]) i2 = e;
        float v1 = p[i1], v2 = p[i2], s2 = 1.f/(v1+v2);
        g_topi[2*t]=i1; g_topi[2*t+1]=i2;
        g_topv[2*t]=v1*s2; g_topv[2*t+1]=v2*s2;
    }
}

// ---------------- deterministic per-expert token lists ----------------
__global__ void assign_kernel()
{
    __shared__ int scn[256];
    int tid = threadIdx.x;
    int base = 0;
    for (int e=0;e<NEXP;e++){
        int fl[8]; float fw[8];
        int local = 0;
        #pragma unroll
        for (int j=0;j<8;j++){
            int t = tid*8 + j;
            int a = g_topi[2*t], b = g_topi[2*t+1];
            float w = 0.f; int f = 0;
            if (a==e){ w += g_topv[2*t];   f = 1; }
            if (b==e){ w += g_topv[2*t+1]; f = 1; }
            fl[j]=f; fw[j]=w; local += f;
        }
        scn[tid]=local;
        __syncthreads();
        for (int d=1; d<256; d<<=1){
            int v = (tid>=d) ? scn[tid-d] : 0;
            __syncthreads();
            scn[tid] += v;
            __syncthreads();
        }
        int pos   = base + scn[tid] - local;
        int total = scn[255];
        #pragma unroll
        for (int j=0;j<8;j++){
            if (fl[j]){ g_tok[pos]=tid*8+j; g_wgt[pos]=fw[j]; pos++; }
        }
        if (tid==0){ g_cnt[e]=total; g_off[e]=base; }
        base += total;
        __syncthreads();
    }
}

// ---------------- swiglu: t1 = silu(t1)*t3, write fp16 hi/lo ----------------
__global__ void swiglu_kernel()
{
    size_t i = ((size_t)blockIdx.x*256 + threadIdx.x)*4;
    float4 a = *(const float4*)(g_t1+i);
    float4 b = *(const float4*)(g_t3+i);
    float v0 = a.x*b.x/(1.f+__expf(-a.x));
    float v1 = a.y*b.y/(1.f+__expf(-a.y));
    float v2 = a.z*b.z/(1.f+__expf(-a.z));
    float v3 = a.w*b.w/(1.f+__expf(-a.w));
    fp16 h0,l0,h1,l1,h2,l2,h3,l3;
    split2h(v0,h0,l0); split2h(v1,h1,l1); split2h(v2,h2,l2); split2h(v3,h3,l3);
    __half2 ph0; ph0.x=h0; ph0.y=h1;
    __half2 ph1; ph1.x=h2; ph1.y=h3;
    __half2 pl0; pl0.x=l0; pl0.y=l1;
    __half2 pl1; pl1.x=l2; pl1.y=l3;
    *(__half2*)(g_t1hi+i)   = ph0;
    *(__half2*)(g_t1hi+i+2) = ph1;
    *(__half2*)(g_t1lo+i)   = pl0;
    *(__half2*)(g_t1lo+i+2) = pl1;
}

// ---------------- base: out = h ----------------
__global__ void copy_h_kernel(float* __restrict__ out)
{
    int i = blockIdx.x*256 + threadIdx.x;
    out[i] = g_h[i];
}

// ---------------- launch ----------------
extern "C" void kernel_launch(void* const* d_in, const int* in_sizes, int n_in,
                              void* d_out, int out_size)
{
    (void)in_sizes; (void)n_in; (void)out_size;
    const float* hidden = (const float*)d_in[0];
    const float* ln1_w  = (const float*)d_in[1];
    const float* ln2_w  = (const float*)d_in[2];
    const float* q_w    = (const float*)d_in[3];
    const float* k_w    = (const float*)d_in[4];
    const float* v_w    = (const float*)d_in[5];
    const float* o_w    = (const float*)d_in[6];
    const float* gate_w = (const float*)d_in[7];
    const float* w1     = (const float*)d_in[8];
    const float* w3     = (const float*)d_in[9];
    const float* w2     = (const float*)d_in[10];
    float* out = (float*)d_out;

    cudaFuncSetAttribute(mma_gemm, cudaFuncAttributeMaxDynamicSharedMemorySize, SMEM_DYN);

    // weight conversion fp32 -> fp16 (selectors: 0 q,1 k,2 v,3 o,4 w1,5 w3,6 w2)
    cvt_kernel<<<(HID*HID/8+255)/256,256>>>(q_w, 0, (size_t)HID*HID);
    cvt_kernel<<<(KVDIM*HID/8+255)/256,256>>>(k_w, 1, (size_t)KVDIM*HID);
    cvt_kernel<<<(KVDIM*HID/8+255)/256,256>>>(v_w, 2, (size_t)KVDIM*HID);
    cvt_kernel<<<(HID*HID/8+255)/256,256>>>(o_w, 3, (size_t)HID*HID);
    cvt_kernel<<<(unsigned)((size_t)NEXP*FFD*HID/8/256),256>>>(w1, 4, (size_t)NEXP*FFD*HID);
    cvt_kernel<<<(unsigned)((size_t)NEXP*FFD*HID/8/256),256>>>(w3, 5, (size_t)NEXP*FFD*HID);
    cvt_kernel<<<(unsigned)((size_t)NEXP*HID*FFD/8/256),256>>>(w2, 6, (size_t)NEXP*HID*FFD);

    // attention block
    rmsnorm_kernel<<<SEQ,256>>>(hidden, ln1_w, 0);
    mma_gemm<<<dim3(HID/128,   SEQ/128, 1), 256, SMEM_DYN>>>(0, 0, 0, 0, 0, (float*)0, (const float*)0, HID, HID,   0);
    // fused K+V projections (z=0 -> k, z=1 -> v)
    mma_gemm<<<dim3(KVDIM/128, SEQ/128, 2), 256, SMEM_DYN>>>(0, 1, 1, 2, 2, (float*)0, (const float*)0, HID, KVDIM, 0);
    rope_kernel<<<(SEQ*(HID/2))/256,  256>>>(0);
    rope_kernel<<<(SEQ*(KVDIM/2))/256,256>>>(1);
    flash_attn_kernel<<<dim3(SEQ/64, NHEAD),256>>>();
    mma_gemm<<<dim3(HID/128, SEQ/128, 1), 256, SMEM_DYN>>>(1, 3, 3, 0, 0, (float*)0, hidden, HID, HID, 1);

    // MoE block
    rmsnorm_kernel<<<SEQ,256>>>((const float*)0, ln2_w, 1);
    route_kernel<<<SEQ,256>>>(gate_w);
    assign_kernel<<<1,256>>>();
    // fused w1 (z<8) + w3 (z>=8)
    mma_gemm<<<dim3(FFD/128, SEQ/128, 2*NEXP), 256, SMEM_DYN>>>(2, 0, 0, 0, 0, (float*)0, (const float*)0, HID, FFD, 2);
    swiglu_kernel<<<(unsigned)((size_t)NASSIGN*FFD/4/256),256>>>();
    copy_h_kernel<<<(SEQ*HID)/256,256>>>(out);
    mma_gemm<<<dim3(HID/128, SEQ/128, NEXP), 256, SMEM_DYN>>>(3, 6, -1, 0, 0, out, (const float*)0, FFD, HID, 3);
}

// round 12
// speedup vs baseline: 1.7750x; 1.1091x over previous
#include <cuda_runtime.h>
#include <cuda_bf16.h>
#include <cuda_fp16.h>
#include <cstdint>
#include <math.h>

#define SEQ   2048
#define HID   2048
#define HDIM  128
#define NHEAD 16
#define KVDIM 512
#define FFD   4096
#define NEXP  8
#define NASSIGN (2*SEQ)
#define PITCH 40
#define TB    (128*PITCH)            // halves per operand tile
#define SMEM_DYN (2*2*TB*2)          // 2 stages x 2 arrays x 128x40 fp16 = 40960 B

typedef __half fp16;
typedef unsigned int u32;

// ---------------- scratch (device globals: allocation-free rule) ----------------
__device__ float g_q[SEQ*HID];
__device__ float g_k[SEQ*KVDIM];
__device__ float g_v[SEQ*KVDIM];
__device__ float g_h[SEQ*HID];
__device__ float g_t1[NASSIGN*FFD];
__device__ float g_t3[NASSIGN*FFD];

__device__ fp16  g_x[SEQ*HID];        // rmsnorm1 out (fp16)
__device__ fp16  g_x2[SEQ*HID];       // rmsnorm2 out (fp16, GEMM operand)
__device__ fp16  g_x2lo[SEQ*HID];     // rmsnorm2 residual (routing only)
__device__ fp16  g_a[SEQ*HID];        // attention out (fp16)
__device__ fp16  g_t1h[NASSIGN*FFD];  // swiglu out (fp16)

__device__ fp16  g_qw[HID*HID];
__device__ fp16  g_kw[KVDIM*HID];
__device__ fp16  g_vw[KVDIM*HID];
__device__ fp16  g_ow[HID*HID];
__device__ fp16  g_w1[NEXP*FFD*HID];
__device__ fp16  g_w3[NEXP*FFD*HID];
__device__ fp16  g_w2[NEXP*HID*FFD];

__device__ int   g_topi[SEQ*2];
__device__ float g_topv[SEQ*2];
__device__ int   g_tok[NASSIGN];
__device__ float g_wgt[NASSIGN];
__device__ int   g_cnt[NEXP];
__device__ int   g_off[NEXP];

// ---------------- helpers ----------------
__device__ __forceinline__ void split2h(float v, fp16& h, fp16& l){
    h = __float2half(v);
    l = __float2half(v - __half2float(h));
}

__device__ __forceinline__ void ldsm4(u32& r0, u32& r1, u32& r2, u32& r3, const fp16* p){
    u32 a = (u32)__cvta_generic_to_shared(p);
    asm volatile("ldmatrix.sync.aligned.m8n8.x4.shared.b16 {%0,%1,%2,%3}, [%4];"
        : "=r"(r0), "=r"(r1), "=r"(r2), "=r"(r3) : "r"(a));
}

__device__ __forceinline__ void mma_f16(float* c, const u32* a, const u32* b){
    asm volatile("mma.sync.aligned.m16n8k16.row.col.f32.f16.f16.f32 "
        "{%0,%1,%2,%3}, {%4,%5,%6,%7}, {%8,%9}, {%0,%1,%2,%3};"
        : "+f"(c[0]), "+f"(c[1]), "+f"(c[2]), "+f"(c[3])
        : "r"(a[0]), "r"(a[1]), "r"(a[2]), "r"(a[3]), "r"(b[0]), "r"(b[1]));
}

__device__ __forceinline__ void cp16(u32 dst, const void* src){
    asm volatile("cp.async.cg.shared.global [%0], [%1], 16;" :: "r"(dst), "l"(src));
}

// weight selector (device side)
__device__ __forceinline__ const fp16* sel_w(int s){
    switch (s){
        case 0: return g_qw;
        case 1: return g_kw;
        case 2: return g_vw;
        case 3: return g_ow;
        case 4: return g_w1;
        case 5: return g_w3;
        default: return g_w2;
    }
}

__device__ __forceinline__ const fp16* sel_a(int s){
    switch (s){
        case 0: return g_x;
        case 1: return g_a;
        case 2: return g_x2;
        default: return g_t1h;
    }
}

__device__ __forceinline__ float* sel_c(int s, float* ext){
    switch (s){
        case 0: return g_q;
        case 1: return g_k;
        case 2: return g_v;
        case 3: return g_h;
        case 4: return g_t1;
        case 5: return g_t3;
        default: return ext;
    }
}

// ---------------- fp32 -> fp16 conversion (8 elems/thread, 16B stores) ----------------
__global__ void cvt_kernel(const float* __restrict__ src, int wsel, size_t n)
{
    fp16* dst = (fp16*)sel_w(wsel);
    size_t i = ((size_t)blockIdx.x*256 + threadIdx.x)*8;
    if (i >= n) return;
    float4 a = *(const float4*)(src + i);
    float4 b = *(const float4*)(src + i + 4);
    __half2 h0 = __floats2half2_rn(a.x, a.y);
    __half2 h1 = __floats2half2_rn(a.z, a.w);
    __half2 h2 = __floats2half2_rn(b.x, b.y);
    __half2 h3 = __floats2half2_rn(b.z, b.w);
    *(uint4*)(dst + i) = make_uint4(*(u32*)&h0, *(u32*)&h1, *(u32*)&h2, *(u32*)&h3);
}

// ---------------- rmsnorm: mode 0 -> g_x ; mode 1 -> g_x2 + g_x2lo (reads g_h) --------
__global__ void rmsnorm_kernel(const float* __restrict__ in_ext, const float* __restrict__ w, int mode)
{
    const float* in = mode ? (const float*)g_h : in_ext;
    fp16* hi = mode ? g_x2 : g_x;
    int row = blockIdx.x;
    const float* x = in + (size_t)row*HID;
    __shared__ float red[256];
    float ss = 0.f;
    for (int i = threadIdx.x; i < HID; i += 256) { float v = x[i]; ss += v*v; }
    red[threadIdx.x] = ss; __syncthreads();
    for (int s = 128; s > 0; s >>= 1) {
        if (threadIdx.x < s) red[threadIdx.x] += red[threadIdx.x+s];
        __syncthreads();
    }
    float rs = rsqrtf(red[0]/(float)HID + 1e-5f);
    size_t base = (size_t)row*HID;
    for (int i = threadIdx.x; i < HID; i += 256){
        float v = x[i]*rs*w[i];
        fp16 h,l; split2h(v,h,l);
        hi[base+i]=h;
        if (mode) g_x2lo[base+i]=l;     // exact logits for routing
    }
}

// ---------------- MMA GEMM: C = A * B^T (fp16, fp32 accum, cp.async 2-stage) ----------------
// mode 0: dense (z picks (bsel,csel) or (b2,c2)) | 1: dense + addend
// mode 2: moe gather-in (z&7 = expert, z>=8 -> w3/t3) | 3: moe scatter-out (z = expert)
__global__ __launch_bounds__(256,2) void mma_gemm(
    int asel, int bsel, int csel, int b2, int c2,
    float* __restrict__ Cext, const float* __restrict__ addend,
    int K, int N, int mode)
{
    extern __shared__ __align__(16) fp16 dsm[];
    u32 sbase = (u32)__cvta_generic_to_shared(dsm);

    int z = blockIdx.z;
    if (mode <= 1 && z == 1){ bsel = b2; csel = c2; }
    int expt = 0;
    if (mode == 2){ expt = z & 7; bsel = (z >= 8) ? 5 : 4; csel = bsel; }
    if (mode == 3) expt = z;

    const fp16* A = sel_a(asel);
    const fp16* B = sel_w(bsel);
    float* C = sel_c(csel, Cext);

    int tid = threadIdx.x, lane = tid & 31, wid = tid >> 5;
    int m0 = blockIdx.y*128, n0 = blockIdx.x*128;
    int cnt = 0, off = 0;
    if (mode >= 2){
        cnt = g_cnt[expt]; off = g_off[expt];
        if (m0 >= cnt) return;
        B += (size_t)expt*N*K;
    }

    int sr = tid >> 1, sh = (tid & 1)*16;
    int arow;
    if (mode == 2)      arow = g_tok[off + min(m0+sr, cnt-1)];
    else if (mode == 3) arow = off + min(m0+sr, cnt-1);
    else                arow = m0 + sr;
    const fp16* psrc[2];
    psrc[0] = A + (size_t)arow*K + sh;
    psrc[1] = B + (size_t)(n0+sr)*K + sh;
    u32 soff = (u32)(sr*PITCH + sh)*2;

    float acc[4][4][4];
    #pragma unroll
    for (int mi=0;mi<4;mi++)
        #pragma unroll
        for (int ni=0;ni<4;ni++)
            #pragma unroll
            for (int r=0;r<4;r++) acc[mi][ni][r]=0.f;

    int wm = (wid & 1)*64, wn = (wid >> 1)*32;
    int niter = K >> 5;

    #pragma unroll
    for (int a2=0;a2<2;a2++){
        u32 d = sbase + (u32)(a2*TB*2) + soff;
        cp16(d, psrc[a2]);
        cp16(d+16, psrc[a2]+8);
    }
    asm volatile("cp.async.commit_group;");

    for (int it=0; it<niter; it++){
        if (it+1 < niter){
            int st = (it+1)&1;
            int k0 = (it+1)<<5;
            #pragma unroll
            for (int a2=0;a2<2;a2++){
                u32 d = sbase + (u32)((st*2+a2)*TB*2) + soff;
                cp16(d, psrc[a2]+k0);
                cp16(d+16, psrc[a2]+k0+8);
            }
        }
        asm volatile("cp.async.commit_group;");
        asm volatile("cp.async.wait_group 1;");
        __syncthreads();

        int cur = it&1;
        fp16* bA = dsm + (cur*2+0)*TB;
        fp16* bB = dsm + (cur*2+1)*TB;

        #pragma unroll
        for (int ks=0; ks<32; ks+=16){
            u32 fa[4][4], fb[4][2];
            int ar = lane & 15;
            int ac = ks + ((lane >> 4) << 3);
            #pragma unroll
            for (int mi=0;mi<4;mi++){
                ldsm4(fa[mi][0],fa[mi][1],fa[mi][2],fa[mi][3], &bA[(wm+mi*16+ar)*PITCH + ac]);
            }
            int br = ((lane >> 4) << 3) + (lane & 7);
            int bc = ks + (((lane >> 3) & 1) << 3);
            #pragma unroll
            for (int np=0;np<2;np++){
                ldsm4(fb[np*2][0],fb[np*2][1],fb[np*2+1][0],fb[np*2+1][1], &bB[(wn+np*16+br)*PITCH + bc]);
            }
            #pragma unroll
            for (int mi=0;mi<4;mi++)
                #pragma unroll
                for (int ni=0;ni<4;ni++)
                    mma_f16(acc[mi][ni], fa[mi], fb[ni]);
        }
        __syncthreads();
    }

    int tr = lane >> 2, tc = (lane & 3)*2;
    if (mode <= 1){
        #pragma unroll
        for (int mi=0;mi<4;mi++)
            #pragma unroll
            for (int hh=0;hh<2;hh++){
                int row = m0 + wm + mi*16 + tr + hh*8;
                float* cp = C + (size_t)row*N + n0 + wn;
                #pragma unroll
                for (int ni=0;ni<4;ni++){
                    float v0 = acc[mi][ni][hh*2], v1 = acc[mi][ni][hh*2+1];
                    if (mode==1){
                        const float* ap = addend + (size_t)row*N + n0 + wn;
                        v0 += ap[ni*8+tc]; v1 += ap[ni*8+tc+1];
                    }
                    cp[ni*8+tc] = v0; cp[ni*8+tc+1] = v1;
                }
            }
    } else if (mode == 2){
        #pragma unroll
        for (int mi=0;mi<4;mi++)
            #pragma unroll
            for (int hh=0;hh<2;hh++){
                int slot = m0 + wm + mi*16 + tr + hh*8;
                if (slot < cnt){
                    float* cp = C + (size_t)(off+slot)*N + n0 + wn;
                    #pragma unroll
                    for (int ni=0;ni<4;ni++){
                        cp[ni*8+tc]   = acc[mi][ni][hh*2];
                        cp[ni*8+tc+1] = acc[mi][ni][hh*2+1];
                    }
                }
            }
    } else {
        #pragma unroll
        for (int mi=0;mi<4;mi++)
            #pragma unroll
            for (int hh=0;hh<2;hh++){
                int slot = m0 + wm + mi*16 + tr + hh*8;
                if (slot < cnt){
                    int tok = g_tok[off+slot];
                    float w = g_wgt[off+slot];
                    float* op = C + (size_t)tok*HID + n0 + wn;
                    #pragma unroll
                    for (int ni=0;ni<4;ni++){
                        atomicAdd(&op[ni*8+tc],   w*acc[mi][ni][hh*2]);
                        atomicAdd(&op[ni*8+tc+1], w*acc[mi][ni][hh*2+1]);
                    }
                }
            }
    }
}

// ---------------- RoPE (in-place on g_q / g_k) ----------------
__global__ void rope_kernel(int isK)
{
    int ncols = isK ? KVDIM : HID;
    int half  = ncols >> 1;
    int idx = blockIdx.x*256 + threadIdx.x;
    if (idx >= SEQ*half) return;
    int t = idx / half;
    int p = idx - t*half;
    int head = p >> 6;
    int d = p & 63;
    float* buf = isK ? g_k : g_q;
    int c1 = head*HDIM + d;
    float inv = expf(-(float)d * (9.210340371976184f/64.f));
    float ang = (float)t * inv;
    float cs = cosf(ang), sn = sinf(ang);
    float* b1 = buf + (size_t)t*ncols + c1;
    float x1 = b1[0], x2 = b1[64];
    b1[0]  = x1*cs - x2*sn;
    b1[64] = x2*cs + x1*sn;
}

// ---------------- flash attention (causal, GQA 4:1), writes fp16 ----------------
__global__ __launch_bounds__(256,1) void flash_attn_kernel()
{
    __shared__ float KV[64][128];
    int qt = blockIdx.x, h = blockIdx.y;
    int kvh = h >> 2;
    int tid = threadIdx.x;
    int row = tid >> 2;
    int quar = tid & 3;
    int qrow = qt*64 + row;
    const float scale = 0.08838834764831845f;
    float qreg[32];
    const float4* qp = (const float4*)&g_q[(size_t)qrow*HID + h*HDIM + quar*32];
    #pragma unroll
    for (int i=0;i<8;i++){
        float4 v = qp[i];
        qreg[4*i+0]=v.x*scale; qreg[4*i+1]=v.y*scale;
        qreg[4*i+2]=v.z*scale; qreg[4*i+3]=v.w*scale;
    }
    float m = -1e30f, l = 0.f;
    float o[32];
    #pragma unroll
    for (int i=0;i<32;i++) o[i]=0.f;

    for (int kt = 0; kt <= qt; kt++){
        int k0 = kt*64;
        __syncthreads();
        {
            const float4* src = (const float4*)&g_k[(size_t)(k0+row)*KVDIM + kvh*HDIM + quar*32];
            float4* dst = (float4*)&KV[row][quar*32];
            #pragma unroll
            for (int i=0;i<8;i++) dst[i]=src[i];
        }
        __syncthreads();
        float s[64];
        #pragma unroll
        for (int j=0;j<64;j++){
            const float4* kp = (const float4*)&KV[j][quar*32];
            float acc = 0.f;
            #pragma unroll
            for (int i=0;i<8;i++){
                float4 kv = kp[i];
                acc += qreg[4*i+0]*kv.x + qreg[4*i+1]*kv.y
                     + qreg[4*i+2]*kv.z + qreg[4*i+3]*kv.w;
            }
            acc += __shfl_xor_sync(0xffffffffu, acc, 1);
            acc += __shfl_xor_sync(0xffffffffu, acc, 2);
            s[j] = acc;
        }
        if (kt == qt){
            #pragma unroll
            for (int j=0;j<64;j++) if (k0+j > qrow) s[j] = -1e30f;
        }
        float nm = m;
        #pragma unroll
        for (int j=0;j<64;j++) nm = fmaxf(nm, s[j]);
        float corr = __expf(m - nm);
        float ls = 0.f;
        #pragma unroll
        for (int j=0;j<64;j++){ s[j] = __expf(s[j]-nm); ls += s[j]; }
        l = l*corr + ls;
        #pragma unroll
        for (int i=0;i<32;i++) o[i] *= corr;
        m = nm;
        __syncthreads();
        {
            const float4* src = (const float4*)&g_v[(size_t)(k0+row)*KVDIM + kvh*HDIM + quar*32];
            float4* dst = (float4*)&KV[row][quar*32];
            #pragma unroll
            for (int i=0;i<8;i++) dst[i]=src[i];
        }
        __syncthreads();
        #pragma unroll
        for (int j=0;j<64;j++){
            float p = s[j];
            const float4* vp = (const float4*)&KV[j][quar*32];
            #pragma unroll
            for (int i=0;i<8;i++){
                float4 vv = vp[i];
                o[4*i+0]+=p*vv.x; o[4*i+1]+=p*vv.y;
                o[4*i+2]+=p*vv.z; o[4*i+3]+=p*vv.w;
            }
        }
    }
    float invl = 1.f/l;
    size_t base = (size_t)qrow*HID + h*HDIM + quar*32;
    #pragma unroll
    for (int i=0;i<32;i+=2){
        __half2 ph = __floats2half2_rn(o[i]*invl, o[i+1]*invl);
        *(__half2*)(g_a+base+i) = ph;
    }
}

// ---------------- routing (reconstruct x2 = hi+lo, exact to ~1e-7) ----------------
__global__ void route_kernel(const float* __restrict__ gate_w)
{
    int t = blockIdx.x;
    int wid = threadIdx.x >> 5, lane = threadIdx.x & 31;
    __shared__ float slog[NEXP];
    const fp16* xh = g_x2   + (size_t)t*HID;
    const fp16* xl = g_x2lo + (size_t)t*HID;
    const float* gw = gate_w + (size_t)wid*HID;
    float acc = 0.f;
    for (int i = lane; i < HID; i += 32)
        acc += (__half2float(xh[i]) + __half2float(xl[i]))*gw[i];
    #pragma unroll
    for (int o=16;o;o>>=1) acc += __shfl_xor_sync(0xffffffffu, acc, o);
    if (lane == 0) slog[wid] = acc;
    __syncthreads();
    if (threadIdx.x == 0){
        float mx = slog[0];
        for (int e=1;e<NEXP;e++) mx = fmaxf(mx, slog[e]);
        float p[NEXP]; float se = 0.f;
        for (int e=0;e<NEXP;e++){ p[e] = expf(slog[e]-mx); se += p[e]; }
        float inv = 1.f/se;
        for (int e=0;e<NEXP;e++) p[e] *= inv;
        int i1 = 0;
        for (int e=1;e<NEXP;e++) if (p[e] > p[i1]) i1 = e;
        int i2 = (i1==0) ? 1 : 0;
        for (int e=0;e<NEXP;e++) if (e!=i1 && p[e] > p[i2]) i2 = e;
        float v1 = p[i1], v2 = p[i2], s2 = 1.f/(v1+v2);
        g_topi[2*t]=i1; g_topi[2*t+1]=i2;
        g_topv[2*t]=v1*s2; g_topv[2*t+1]=v2*s2;
    }
}

// ---------------- deterministic per-expert token lists ----------------
__global__ void assign_kernel()
{
    __shared__ int scn[256];
    int tid = threadIdx.x;
    int base = 0;
    for (int e=0;e<NEXP;e++){
        int fl[8]; float fw[8];
        int local = 0;
        #pragma unroll
        for (int j=0;j<8;j++){
            int t = tid*8 + j;
            int a = g_topi[2*t], b = g_topi[2*t+1];
            float w = 0.f; int f = 0;
            if (a==e){ w += g_topv[2*t];   f = 1; }
            if (b==e){ w += g_topv[2*t+1]; f = 1; }
            fl[j]=f; fw[j]=w; local += f;
        }
        scn[tid]=local;
        __syncthreads();
        for (int d=1; d<256; d<<=1){
            int v = (tid>=d) ? scn[tid-d] : 0;
            __syncthreads();
            scn[tid] += v;
            __syncthreads();
        }
        int pos   = base + scn[tid] - local;
        int total = scn[255];
        #pragma unroll
        for (int j=0;j<8;j++){
            if (fl[j]){ g_tok[pos]=tid*8+j; g_wgt[pos]=fw[j]; pos++; }
        }
        if (tid==0){ g_cnt[e]=total; g_off[e]=base; }
        base += total;
        __syncthreads();
    }
}

// ---------------- swiglu: t1h = fp16(silu(t1)*t3) ----------------
__global__ void swiglu_kernel()
{
    size_t i = ((size_t)blockIdx.x*256 + threadIdx.x)*4;
    float4 a = *(const float4*)(g_t1+i);
    float4 b = *(const float4*)(g_t3+i);
    float v0 = a.x*b.x/(1.f+__expf(-a.x));
    float v1 = a.y*b.y/(1.f+__expf(-a.y));
    float v2 = a.z*b.z/(1.f+__expf(-a.z));
    float v3 = a.w*b.w/(1.f+__expf(-a.w));
    __half2 p0 = __floats2half2_rn(v0, v1);
    __half2 p1 = __floats2half2_rn(v2, v3);
    *(__half2*)(g_t1h+i)   = p0;
    *(__half2*)(g_t1h+i+2) = p1;
}

// ---------------- base: out = h ----------------
__global__ void copy_h_kernel(float* __restrict__ out)
{
    int i = blockIdx.x*256 + threadIdx.x;
    out[i] = g_h[i];
}

// ---------------- launch ----------------
extern "C" void kernel_launch(void* const* d_in, const int* in_sizes, int n_in,
                              void* d_out, int out_size)
{
    (void)in_sizes; (void)n_in; (void)out_size;
    const float* hidden = (const float*)d_in[0];
    const float* ln1_w  = (const float*)d_in[1];
    const float* ln2_w  = (const float*)d_in[2];
    const float* q_w    = (const float*)d_in[3];
    const float* k_w    = (const float*)d_in[4];
    const float* v_w    = (const float*)d_in[5];
    const float* o_w    = (const float*)d_in[6];
    const float* gate_w = (const float*)d_in[7];
    const float* w1     = (const float*)d_in[8];
    const float* w3     = (const float*)d_in[9];
    const float* w2     = (const float*)d_in[10];
    float* out = (float*)d_out;

    cudaFuncSetAttribute(mma_gemm, cudaFuncAttributeMaxDynamicSharedMemorySize, SMEM_DYN);

    // weight conversion fp32 -> fp16 (selectors: 0 q,1 k,2 v,3 o,4 w1,5 w3,6 w2)
    cvt_kernel<<<(HID*HID/8+255)/256,256>>>(q_w, 0, (size_t)HID*HID);
    cvt_kernel<<<(KVDIM*HID/8+255)/256,256>>>(k_w, 1, (size_t)KVDIM*HID);
    cvt_kernel<<<(KVDIM*HID/8+255)/256,256>>>(v_w, 2, (size_t)KVDIM*HID);
    cvt_kernel<<<(HID*HID/8+255)/256,256>>>(o_w, 3, (size_t)HID*HID);
    cvt_kernel<<<(unsigned)((size_t)NEXP*FFD*HID/8/256),256>>>(w1, 4, (size_t)NEXP*FFD*HID);
    cvt_kernel<<<(unsigned)((size_t)NEXP*FFD*HID/8/256),256>>>(w3, 5, (size_t)NEXP*FFD*HID);
    cvt_kernel<<<(unsigned)((size_t)NEXP*HID*FFD/8/256),256>>>(w2, 6, (size_t)NEXP*HID*FFD);

    // attention block
    rmsnorm_kernel<<<SEQ,256>>>(hidden, ln1_w, 0);
    mma_gemm<<<dim3(HID/128,   SEQ/128, 1), 256, SMEM_DYN>>>(0, 0, 0, 0, 0, (float*)0, (const float*)0, HID, HID,   0);
    // fused K+V projections (z=0 -> k, z=1 -> v)
    mma_gemm<<<dim3(KVDIM/128, SEQ/128, 2), 256, SMEM_DYN>>>(0, 1, 1, 2, 2, (float*)0, (const float*)0, HID, KVDIM, 0);
    rope_kernel<<<(SEQ*(HID/2))/256,  256>>>(0);
    rope_kernel<<<(SEQ*(KVDIM/2))/256,256>>>(1);
    flash_attn_kernel<<<dim3(SEQ/64, NHEAD),256>>>();
    mma_gemm<<<dim3(HID/128, SEQ/128, 1), 256, SMEM_DYN>>>(1, 3, 3, 0, 0, (float*)0, hidden, HID, HID, 1);

    // MoE block
    rmsnorm_kernel<<<SEQ,256>>>((const float*)0, ln2_w, 1);
    route_kernel<<<SEQ,256>>>(gate_w);
    assign_kernel<<<1,256>>>();
    // fused w1 (z<8) + w3 (z>=8)
    mma_gemm<<<dim3(FFD/128, SEQ/128, 2*NEXP), 256, SMEM_DYN>>>(2, 0, 0, 0, 0, (float*)0, (const float*)0, HID, FFD, 2);
    swiglu_kernel<<<(unsigned)((size_t)NASSIGN*FFD/4/256),256>>>();
    copy_h_kernel<<<(SEQ*HID)/256,256>>>(out);
    mma_gemm<<<dim3(HID/128, SEQ/128, NEXP), 256, SMEM_DYN>>>(3, 6, -1, 0, 0, out, (const float*)0, FFD, HID, 3);
}